// round 2
// baseline (speedup 1.0000x reference)
#include <cuda_runtime.h>

typedef unsigned long long ull;
#define DEVINL __device__ __forceinline__

static constexpr int Bb = 8, Ll = 2048, Dd = 64;
static constexpr int TQ = 128, TK = 128, NT = 256;
static constexpr int NTILES = Ll / TK;
// fold 1/sqrt(64) and log2(e) into Q so softmax exp becomes exp2
static constexpr float QSCALE = 0.18033688011112042f; // log2(e)/8

struct Smem {
    float Qt[64][132];   // Q transposed [d][row], pre-scaled
    float Kt[64][132];   // K tile transposed [d][col]
    float Vs[128][68];   // V tile natural [row][d]
    float Ps[128][132];  // P transposed [col][row]; reused as Osum in epilogue
    float km[128];
    float denom[128];
};

DEVINL ull pack2(float x, float y) {
    ull r; asm("mov.b64 %0, {%1, %2};" : "=l"(r) : "f"(x), "f"(y)); return r;
}
DEVINL void unpack2(ull v, float& x, float& y) {
    asm("mov.b64 {%0, %1}, %2;" : "=f"(x), "=f"(y) : "l"(v));
}
DEVINL void fma2(ull& a, ull x, ull y) {
    asm("fma.rn.f32x2 %0, %1, %2, %0;" : "+l"(a) : "l"(x), "l"(y));
}

// exp2 on the FMA pipe (MUFU would be the bottleneck at 0.5 op/cyc/SM)
DEVINL float fexp2(float x) {
    x = fminf(fmaxf(x, -125.0f), 125.0f);
    float n = rintf(x);
    float f = x - n;                       // [-0.5, 0.5]
    float p = 1.3333558146e-3f;
    p = fmaf(p, f, 9.6181291076e-3f);
    p = fmaf(p, f, 5.5504108664e-2f);
    p = fmaf(p, f, 2.4022650696e-1f);
    p = fmaf(p, f, 6.9314718056e-1f);
    p = fmaf(p, f, 1.0f);
    int ni = (int)n;
    float sc = __int_as_float((ni + 127) << 23); // 2^n
    return p * sc;
}

// Load a 128x64 fp32 tile and store transposed T[d][row] (optionally scaled).
// Lane-fastest over row-blocks -> conflict-free smem stores (scattered gmem,
// L2-resident so acceptable).
template <bool SC>
DEVINL void load_T(const float* __restrict__ g, float (*T)[132], int tid) {
#pragma unroll
    for (int it = 0; it < 2; ++it) {
        int blk = tid + it * NT;        // 0..511
        int bi = (blk & 31) << 2;       // row block 0..124
        int bj = (blk >> 5) << 2;       // d   block 0..60
        float4 r0 = *reinterpret_cast<const float4*>(g + (bi + 0) * Dd + bj);
        float4 r1 = *reinterpret_cast<const float4*>(g + (bi + 1) * Dd + bj);
        float4 r2 = *reinterpret_cast<const float4*>(g + (bi + 2) * Dd + bj);
        float4 r3 = *reinterpret_cast<const float4*>(g + (bi + 3) * Dd + bj);
        if (SC) {
            r0.x *= QSCALE; r0.y *= QSCALE; r0.z *= QSCALE; r0.w *= QSCALE;
            r1.x *= QSCALE; r1.y *= QSCALE; r1.z *= QSCALE; r1.w *= QSCALE;
            r2.x *= QSCALE; r2.y *= QSCALE; r2.z *= QSCALE; r2.w *= QSCALE;
            r3.x *= QSCALE; r3.y *= QSCALE; r3.z *= QSCALE; r3.w *= QSCALE;
        }
        *reinterpret_cast<float4*>(&T[bj + 0][bi]) = make_float4(r0.x, r1.x, r2.x, r3.x);
        *reinterpret_cast<float4*>(&T[bj + 1][bi]) = make_float4(r0.y, r1.y, r2.y, r3.y);
        *reinterpret_cast<float4*>(&T[bj + 2][bi]) = make_float4(r0.z, r1.z, r2.z, r3.z);
        *reinterpret_cast<float4*>(&T[bj + 3][bi]) = make_float4(r0.w, r1.w, r2.w, r3.w);
    }
}

__global__ void __launch_bounds__(NT, 1)
attn_kernel(const float* __restrict__ Q, const float* __restrict__ K,
            const float* __restrict__ V, const float* __restrict__ QM,
            const float* __restrict__ KM, float* __restrict__ Out)
{
    extern __shared__ char smem_raw[];
    Smem* sm = reinterpret_cast<Smem*>(smem_raw);

    const int tid = threadIdx.x;
    const int b  = blockIdx.y;
    const int q0 = blockIdx.x * TQ;

    // GEMM1 map: 16x16 thread grid, 8x8 microtile
    const int ty = tid >> 4, tx = tid & 15;
    const int ty8 = ty << 3, tx8 = tx << 3;
    // GEMM2 map: 2 j-groups x (16x8 grid), 8 rows x 8 d-cols
    const int g  = tid >> 7, t2 = tid & 127;
    const int r8 = (t2 >> 3) << 3, c8 = (t2 & 7) << 3;

    const float* Qb = Q + (size_t)(b * Ll + q0) * Dd;
    const float* Kb = K + (size_t)b * Ll * Dd;
    const float* Vb = V + (size_t)b * Ll * Dd;

    load_T<true>(Qb, sm->Qt, tid);

    ull o2[8][4];
#pragma unroll
    for (int i = 0; i < 8; ++i) { o2[i][0] = 0; o2[i][1] = 0; o2[i][2] = 0; o2[i][3] = 0; }
    float rowsum[8] = {0.f, 0.f, 0.f, 0.f, 0.f, 0.f, 0.f, 0.f};

    for (int kt = 0; kt < NTILES; ++kt) {
        __syncthreads();  // prev tile's GEMM2 done reading Vs/Ps before overwrite
        load_T<false>(Kb + (size_t)kt * TK * Dd, sm->Kt, tid);
#pragma unroll
        for (int it = 0; it < 8; ++it) {
            int idx = tid + it * NT;
            int row = idx >> 4, c4 = (idx & 15) << 2;
            *reinterpret_cast<float4*>(&sm->Vs[row][c4]) =
                *reinterpret_cast<const float4*>(Vb + (size_t)(kt * TK + row) * Dd + c4);
        }
        if (tid < TK) sm->km[tid] = KM[b * Ll + kt * TK + tid];
        __syncthreads();

        // ---- GEMM1: S = (Q*scale) @ K^T, packed f32x2 ----
        ull s2[8][4];
#pragma unroll
        for (int i = 0; i < 8; ++i) { s2[i][0] = 0; s2[i][1] = 0; s2[i][2] = 0; s2[i][3] = 0; }
#pragma unroll 8
        for (int d = 0; d < Dd; ++d) {
            float4 a0 = *reinterpret_cast<const float4*>(&sm->Qt[d][ty8]);
            float4 a1 = *reinterpret_cast<const float4*>(&sm->Qt[d][ty8 + 4]);
            ulonglong2 bq0 = *reinterpret_cast<const ulonglong2*>(&sm->Kt[d][tx8]);
            ulonglong2 bq1 = *reinterpret_cast<const ulonglong2*>(&sm->Kt[d][tx8 + 4]);
            ull bb0 = bq0.x, bb1 = bq0.y, bb2 = bq1.x, bb3 = bq1.y;
            float av[8] = {a0.x, a0.y, a0.z, a0.w, a1.x, a1.y, a1.z, a1.w};
#pragma unroll
            for (int i = 0; i < 8; ++i) {
                ull ai = pack2(av[i], av[i]);
                fma2(s2[i][0], ai, bb0);
                fma2(s2[i][1], ai, bb1);
                fma2(s2[i][2], ai, bb2);
                fma2(s2[i][3], ai, bb3);
            }
        }

        // ---- exp2 + k_mask + rowsum ----
        float kmv[8];
#pragma unroll
        for (int j = 0; j < 8; ++j) kmv[j] = sm->km[tx8 + j];
        float p[8][8];
#pragma unroll
        for (int i = 0; i < 8; ++i) {
#pragma unroll
            for (int jp = 0; jp < 4; ++jp) {
                float x0, x1;
                unpack2(s2[i][jp], x0, x1);
                float e0 = fexp2(x0) * kmv[2 * jp];
                float e1 = fexp2(x1) * kmv[2 * jp + 1];
                p[i][2 * jp] = e0;
                p[i][2 * jp + 1] = e1;
                rowsum[i] += e0 + e1;
            }
        }
        // store P transposed: Ps[col][row]
#pragma unroll
        for (int j = 0; j < 8; ++j) {
            *reinterpret_cast<float4*>(&sm->Ps[tx8 + j][ty8]) =
                make_float4(p[0][j], p[1][j], p[2][j], p[3][j]);
            *reinterpret_cast<float4*>(&sm->Ps[tx8 + j][ty8 + 4]) =
                make_float4(p[4][j], p[5][j], p[6][j], p[7][j]);
        }
        __syncthreads();

        // ---- GEMM2: O += P @ V, j split across 2 groups ----
        const int j0 = g << 6;
#pragma unroll 8
        for (int j = 0; j < 64; ++j) {
            int jj = j0 + j;
            float4 a0 = *reinterpret_cast<const float4*>(&sm->Ps[jj][r8]);
            float4 a1 = *reinterpret_cast<const float4*>(&sm->Ps[jj][r8 + 4]);
            ulonglong2 bq0 = *reinterpret_cast<const ulonglong2*>(&sm->Vs[jj][c8]);
            ulonglong2 bq1 = *reinterpret_cast<const ulonglong2*>(&sm->Vs[jj][c8 + 4]);
            ull bb0 = bq0.x, bb1 = bq0.y, bb2 = bq1.x, bb3 = bq1.y;
            float av[8] = {a0.x, a0.y, a0.z, a0.w, a1.x, a1.y, a1.z, a1.w};
#pragma unroll
            for (int i = 0; i < 8; ++i) {
                ull ai = pack2(av[i], av[i]);
                fma2(o2[i][0], ai, bb0);
                fma2(o2[i][1], ai, bb1);
                fma2(o2[i][2], ai, bb2);
                fma2(o2[i][3], ai, bb3);
            }
        }
    }

    // ---- epilogue ----
    __syncthreads();
    float* red = &sm->Kt[0][0];  // 16 x 128 partial rowsums (Kt dead)
#pragma unroll
    for (int i = 0; i < 8; ++i) red[tx * 128 + ty8 + i] = rowsum[i];
    __syncthreads();
    if (tid < TQ) {
        float s = 0.f;
#pragma unroll
        for (int t = 0; t < 16; ++t) s += red[t * 128 + tid];
        float qm = QM[b * Ll + q0 + tid];
        sm->denom[tid] = qm / fmaxf(s, 2e-15f);
    }
    __syncthreads();

    float (*Os)[132] = sm->Ps;  // reuse Ps as the group-1 partial buffer
    if (g == 1) {
#pragma unroll
        for (int i = 0; i < 8; ++i) {
            float v[8];
            unpack2(o2[i][0], v[0], v[1]);
            unpack2(o2[i][1], v[2], v[3]);
            unpack2(o2[i][2], v[4], v[5]);
            unpack2(o2[i][3], v[6], v[7]);
            *reinterpret_cast<float4*>(&Os[r8 + i][c8])     = make_float4(v[0], v[1], v[2], v[3]);
            *reinterpret_cast<float4*>(&Os[r8 + i][c8 + 4]) = make_float4(v[4], v[5], v[6], v[7]);
        }
    }
    __syncthreads();
    if (g == 0) {
#pragma unroll
        for (int i = 0; i < 8; ++i) {
            int row = r8 + i;
            float dv = sm->denom[row];
            float4 u0 = *reinterpret_cast<const float4*>(&Os[row][c8]);
            float4 u1 = *reinterpret_cast<const float4*>(&Os[row][c8 + 4]);
            float v[8];
            unpack2(o2[i][0], v[0], v[1]);
            unpack2(o2[i][1], v[2], v[3]);
            unpack2(o2[i][2], v[4], v[5]);
            unpack2(o2[i][3], v[6], v[7]);
            float* op = Out + (size_t)(b * Ll + q0 + row) * Dd + c8;
            *reinterpret_cast<float4*>(op) =
                make_float4((v[0] + u0.x) * dv, (v[1] + u0.y) * dv,
                            (v[2] + u0.z) * dv, (v[3] + u0.w) * dv);
            *reinterpret_cast<float4*>(op + 4) =
                make_float4((v[4] + u1.x) * dv, (v[5] + u1.y) * dv,
                            (v[6] + u1.z) * dv, (v[7] + u1.w) * dv);
        }
    }
}

extern "C" void kernel_launch(void* const* d_in, const int* in_sizes, int n_in,
                              void* d_out, int out_size) {
    const float* Q  = (const float*)d_in[0];
    const float* K  = (const float*)d_in[1];
    const float* V  = (const float*)d_in[2];
    const float* QM = (const float*)d_in[3];
    const float* KM = (const float*)d_in[4];
    float* Out = (float*)d_out;

    cudaFuncSetAttribute(attn_kernel, cudaFuncAttributeMaxDynamicSharedMemorySize,
                         (int)sizeof(Smem));
    dim3 grid(Ll / TQ, Bb);   // 16 q-tiles x 8 batches = 128 CTAs (1 wave)
    attn_kernel<<<grid, NT, sizeof(Smem)>>>(Q, K, V, QM, KM, Out);
}

// round 4
// speedup vs baseline: 2.3881x; 2.3881x over previous
#include <cuda_runtime.h>

typedef unsigned int u32;
#define DEVINL __device__ __forceinline__

static constexpr int Bb = 8, Ll = 2048, Dd = 64;
static constexpr int TQ = 128, NT = 256, NTILES = 16;
static constexpr float QSCALE = 0.18033688011112042f; // log2(e)/8

// smem byte offsets: bf16 [128][64] tiles, 128B rows, SW128-style XOR swizzle
static constexpr int SM_KH = 0;
static constexpr int SM_KL = 16384;
static constexpr int SM_VH = 32768;
static constexpr int SM_VL = 49152;
static constexpr int SM_KM = 65536;   // 128 f32
static constexpr int SM_TOT = 66048;

DEVINL u32 smem_u32(const void* p) {
    u32 a;
    asm("{ .reg .u64 t; cvta.to.shared.u64 t, %1; cvt.u32.u64 %0, t; }" : "=r"(a) : "l"(p));
    return a;
}
DEVINL u32 swz(u32 o) { return o ^ ((o >> 3) & 0x70); }
DEVINL float ex2f(float x) { float r; asm("ex2.approx.f32 %0, %1;" : "=f"(r) : "f"(x)); return r; }

// hi = truncated bf16 pair (one PRMT): result = (bf16(b)<<16) | bf16(a)
DEVINL u32 pack_hi(float a, float b) {
    return __byte_perm(__float_as_uint(a), __float_as_uint(b), 0x7632);
}
// lo = bf16(x - trunc_bf16(x)) pair, packed (b high, a low)
DEVINL u32 pack_lo(float a, float b) {
    float la = a - __uint_as_float(__float_as_uint(a) & 0xFFFF0000u);
    float lb = b - __uint_as_float(__float_as_uint(b) & 0xFFFF0000u);
    u32 r;
    asm("cvt.rn.satfinite.bf16x2.f32 %0, %1, %2;" : "=r"(r) : "f"(lb), "f"(la));
    return r;
}

DEVINL void ldsm4(u32* r, u32 a) {
    asm volatile("ldmatrix.sync.aligned.m8n8.x4.shared.b16 {%0,%1,%2,%3}, [%4];"
                 : "=r"(r[0]), "=r"(r[1]), "=r"(r[2]), "=r"(r[3]) : "r"(a) : "memory");
}
DEVINL void ldsm4t(u32* r, u32 a) {
    asm volatile("ldmatrix.sync.aligned.m8n8.x4.trans.shared.b16 {%0,%1,%2,%3}, [%4];"
                 : "=r"(r[0]), "=r"(r[1]), "=r"(r[2]), "=r"(r[3]) : "r"(a) : "memory");
}
DEVINL void mma16816(float* c, const u32* a, u32 b0, u32 b1) {
    asm("mma.sync.aligned.m16n8k16.row.col.f32.bf16.bf16.f32 "
        "{%0,%1,%2,%3}, {%4,%5,%6,%7}, {%8,%9}, {%0,%1,%2,%3};"
        : "+f"(c[0]), "+f"(c[1]), "+f"(c[2]), "+f"(c[3])
        : "r"(a[0]), "r"(a[1]), "r"(a[2]), "r"(a[3]), "r"(b0), "r"(b1));
}

// fp32 [128][64] gmem tile -> bf16 hi/lo smem tiles (swizzled 128B rows)
template <bool SC>
DEVINL void load_split(const float* __restrict__ g, char* hi, char* lo, int tid) {
    int row = tid >> 1;
    int c0 = (tid & 1) * 32;
    const float* gp = g + (size_t)row * Dd;
#pragma unroll
    for (int i = 0; i < 4; ++i) {
        int c = c0 + 8 * i;
        float4 a = *reinterpret_cast<const float4*>(gp + c);
        float4 b = *reinterpret_cast<const float4*>(gp + c + 4);
        if (SC) {
            a.x *= QSCALE; a.y *= QSCALE; a.z *= QSCALE; a.w *= QSCALE;
            b.x *= QSCALE; b.y *= QSCALE; b.z *= QSCALE; b.w *= QSCALE;
        }
        uint4 H = make_uint4(pack_hi(a.x, a.y), pack_hi(a.z, a.w),
                             pack_hi(b.x, b.y), pack_hi(b.z, b.w));
        uint4 Lo = make_uint4(pack_lo(a.x, a.y), pack_lo(a.z, a.w),
                              pack_lo(b.x, b.y), pack_lo(b.z, b.w));
        u32 off = swz((u32)(row * 128 + c * 2));
        *reinterpret_cast<uint4*>(hi + off) = H;
        *reinterpret_cast<uint4*>(lo + off) = Lo;
    }
}

__global__ void __launch_bounds__(NT, 1)
attn_mma(const float* __restrict__ Q, const float* __restrict__ K,
         const float* __restrict__ V, const float* __restrict__ QM,
         const float* __restrict__ KM, float* __restrict__ Out)
{
    extern __shared__ char sm[];
    const u32 smb = smem_u32(sm);
    const int tid = threadIdx.x, w = tid >> 5, L = tid & 31;
    const int b = blockIdx.y, q0 = blockIdx.x * TQ;

    const float* Qb = Q + (size_t)(b * Ll + q0) * Dd;
    const float* Kb = K + (size_t)b * Ll * Dd;
    const float* Vb = V + (size_t)b * Ll * Dd;

    // ---- stage Q (scaled) through K smem slots, build resident A fragments ----
    load_split<true>(Qb, sm + SM_KH, sm + SM_KL, tid);
    __syncthreads();

    const int m = L >> 3;                       // ldmatrix sub-matrix index
    const u32 xm = (u32)(L & 7) << 4;           // swizzle XOR for this lane's row
    const int arw = (m & 1) * 8 + (L & 7);      // A/V row-within-16
    const u32 acolsel = (u32)(m >> 1) * 16;
    u32 qh[4][4], ql[4][4];
#pragma unroll
    for (int kc = 0; kc < 4; ++kc) {
        u32 off = (u32)(16 * w + arw) * 128 + (((u32)kc * 32 + acolsel) ^ xm);
        ldsm4(qh[kc], smb + SM_KH + off);
        ldsm4(ql[kc], smb + SM_KL + off);
    }
    // B(K) lane addressing: rows = keys
    const u32 krw_off = (u32)((m >> 1) * 8 + (L & 7)) * 128;
    const u32 kcolsel = (u32)(m & 1) * 16;
    // B(V, trans) lane addressing: rows = keys
    const u32 vrw_off = (u32)arw * 128;
    const u32 vcolsel = (u32)(m >> 1) * 16;

    float oacc[8][4];
#pragma unroll
    for (int j = 0; j < 8; ++j) { oacc[j][0] = 0; oacc[j][1] = 0; oacc[j][2] = 0; oacc[j][3] = 0; }
    float rs0 = 0.f, rs1 = 0.f;

    for (int kt = 0; kt < NTILES; ++kt) {
        __syncthreads();   // previous tile's consumers done with K/V/km smem
        load_split<false>(Kb + (size_t)kt * 128 * Dd, sm + SM_KH, sm + SM_KL, tid);
        load_split<false>(Vb + (size_t)kt * 128 * Dd, sm + SM_VH, sm + SM_VL, tid);
        if (tid < 128)
            reinterpret_cast<float*>(sm + SM_KM)[tid] = KM[b * Ll + kt * 128 + tid];
        __syncthreads();

        // ---- GEMM1: S = Q @ K^T  (bf16x3) ----
        float sacc[16][4];
#pragma unroll
        for (int j = 0; j < 16; ++j) { sacc[j][0] = 0; sacc[j][1] = 0; sacc[j][2] = 0; sacc[j][3] = 0; }
#pragma unroll
        for (int j2 = 0; j2 < 8; ++j2) {
            u32 base = smb + (u32)j2 * 2048 + krw_off;
#pragma unroll
            for (int kc = 0; kc < 4; ++kc) {
                u32 coff = (((u32)kc * 32 + kcolsel) ^ xm);
                u32 bh[4], bl[4];
                ldsm4(bh, base + SM_KH + coff);
                ldsm4(bl, base + SM_KL + coff);
                mma16816(sacc[2 * j2],     qh[kc], bh[0], bh[1]);
                mma16816(sacc[2 * j2],     ql[kc], bh[0], bh[1]);
                mma16816(sacc[2 * j2],     qh[kc], bl[0], bl[1]);
                mma16816(sacc[2 * j2 + 1], qh[kc], bh[2], bh[3]);
                mma16816(sacc[2 * j2 + 1], ql[kc], bh[2], bh[3]);
                mma16816(sacc[2 * j2 + 1], qh[kc], bl[2], bl[3]);
            }
        }

        // ---- fused softmax + GEMM2: O += P @ V  (bf16x3, P stays in registers) ----
        const float* kmp = reinterpret_cast<const float*>(sm + SM_KM);
#pragma unroll
        for (int kc = 0; kc < 8; ++kc) {
            u32 Ah[4], Al[4];
#pragma unroll
            for (int half = 0; half < 2; ++half) {
                int j = 2 * kc + half;
                float2 km2 = *reinterpret_cast<const float2*>(kmp + 8 * j + 2 * (L & 3));
                float p0 = ex2f(sacc[j][0]) * km2.x;
                float p1 = ex2f(sacc[j][1]) * km2.y;
                float p2 = ex2f(sacc[j][2]) * km2.x;
                float p3 = ex2f(sacc[j][3]) * km2.y;
                rs0 += p0 + p1;
                rs1 += p2 + p3;
                Ah[2 * half]     = pack_hi(p0, p1);
                Ah[2 * half + 1] = pack_hi(p2, p3);
                Al[2 * half]     = pack_lo(p0, p1);
                Al[2 * half + 1] = pack_lo(p2, p3);
            }
            u32 base = smb + (u32)kc * 2048 + vrw_off;
#pragma unroll
            for (int j2 = 0; j2 < 4; ++j2) {
                u32 coff = (((u32)j2 * 32 + vcolsel) ^ xm);
                u32 vh[4], vl[4];
                ldsm4t(vh, base + SM_VH + coff);
                ldsm4t(vl, base + SM_VL + coff);
                mma16816(oacc[2 * j2],     Ah, vh[0], vh[1]);
                mma16816(oacc[2 * j2],     Al, vh[0], vh[1]);
                mma16816(oacc[2 * j2],     Ah, vl[0], vl[1]);
                mma16816(oacc[2 * j2 + 1], Ah, vh[2], vh[3]);
                mma16816(oacc[2 * j2 + 1], Al, vh[2], vh[3]);
                mma16816(oacc[2 * j2 + 1], Ah, vl[2], vl[3]);
            }
        }
    }

    // ---- final: quad-reduce rowsums, divide, write ----
    rs0 += __shfl_xor_sync(0xFFFFFFFFu, rs0, 1);
    rs0 += __shfl_xor_sync(0xFFFFFFFFu, rs0, 2);
    rs1 += __shfl_xor_sync(0xFFFFFFFFu, rs1, 1);
    rs1 += __shfl_xor_sync(0xFFFFFFFFu, rs1, 2);

    int r0 = q0 + 16 * w + (L >> 2);
    int r1 = r0 + 8;
    float dv0 = QM[b * Ll + r0] / fmaxf(rs0, 2e-15f);
    float dv1 = QM[b * Ll + r1] / fmaxf(rs1, 2e-15f);

    float* o0 = Out + (size_t)(b * Ll + r0) * Dd + 2 * (L & 3);
    float* o1 = Out + (size_t)(b * Ll + r1) * Dd + 2 * (L & 3);
#pragma unroll
    for (int j = 0; j < 8; ++j) {
        *reinterpret_cast<float2*>(o0 + 8 * j) = make_float2(oacc[j][0] * dv0, oacc[j][1] * dv0);
        *reinterpret_cast<float2*>(o1 + 8 * j) = make_float2(oacc[j][2] * dv1, oacc[j][3] * dv1);
    }
}

extern "C" void kernel_launch(void* const* d_in, const int* in_sizes, int n_in,
                              void* d_out, int out_size) {
    const float* Q  = (const float*)d_in[0];
    const float* K  = (const float*)d_in[1];
    const float* V  = (const float*)d_in[2];
    const float* QM = (const float*)d_in[3];
    const float* KM = (const float*)d_in[4];
    float* Out = (float*)d_out;

    cudaFuncSetAttribute(attn_mma, cudaFuncAttributeMaxDynamicSharedMemorySize, SM_TOT);
    dim3 grid(Ll / TQ, Bb);   // 16 q-tiles x 8 batches = 128 CTAs
    attn_mma<<<grid, NT, SM_TOT>>>(Q, K, V, QM, KM, Out);
}

// round 5
// speedup vs baseline: 2.7061x; 1.1331x over previous
#include <cuda_runtime.h>

typedef unsigned int u32;
#define DEVINL __device__ __forceinline__

static constexpr int Bb = 8, Ll = 2048, Dd = 64;
static constexpr int TQ = 128, NT = 256, NTILES = 16;
static constexpr float QSCALE = 0.18033688011112042f; // log2(e)/8

// double-buffered bf16 tiles: buf s at s*65536; within a buffer:
static constexpr int OF_KH = 0;
static constexpr int OF_KL = 16384;
static constexpr int OF_VH = 32768;
static constexpr int OF_VL = 49152;
static constexpr int SM_KM  = 131072;  // km[2][128] f32
static constexpr int SM_TOT = 132096;

DEVINL u32 smem_u32(const void* p) {
    u32 a;
    asm("{ .reg .u64 t; cvta.to.shared.u64 t, %1; cvt.u32.u64 %0, t; }" : "=r"(a) : "l"(p));
    return a;
}
DEVINL u32 swz(u32 o) { return o ^ ((o >> 3) & 0x70); }
DEVINL float ex2f(float x) { float r; asm("ex2.approx.f32 %0, %1;" : "=f"(r) : "f"(x)); return r; }

// hi = truncated bf16 pair (one PRMT): result = (bf16(b)<<16) | bf16(a)
DEVINL u32 pack_hi(float a, float b) {
    return __byte_perm(__float_as_uint(a), __float_as_uint(b), 0x7632);
}
// lo = bf16(x - trunc_bf16(x)) pair, packed (b high, a low)
DEVINL u32 pack_lo(float a, float b) {
    float la = a - __uint_as_float(__float_as_uint(a) & 0xFFFF0000u);
    float lb = b - __uint_as_float(__float_as_uint(b) & 0xFFFF0000u);
    u32 r;
    asm("cvt.rn.satfinite.bf16x2.f32 %0, %1, %2;" : "=r"(r) : "f"(lb), "f"(la));
    return r;
}

DEVINL void ldsm4(u32* r, u32 a) {
    asm volatile("ldmatrix.sync.aligned.m8n8.x4.shared.b16 {%0,%1,%2,%3}, [%4];"
                 : "=r"(r[0]), "=r"(r[1]), "=r"(r[2]), "=r"(r[3]) : "r"(a) : "memory");
}
DEVINL void ldsm4t(u32* r, u32 a) {
    asm volatile("ldmatrix.sync.aligned.m8n8.x4.trans.shared.b16 {%0,%1,%2,%3}, [%4];"
                 : "=r"(r[0]), "=r"(r[1]), "=r"(r[2]), "=r"(r[3]) : "r"(a) : "memory");
}
DEVINL void mma16816(float* c, const u32* a, u32 b0, u32 b1) {
    asm("mma.sync.aligned.m16n8k16.row.col.f32.bf16.bf16.f32 "
        "{%0,%1,%2,%3}, {%4,%5,%6,%7}, {%8,%9}, {%0,%1,%2,%3};"
        : "+f"(c[0]), "+f"(c[1]), "+f"(c[2]), "+f"(c[3])
        : "r"(a[0]), "r"(a[1]), "r"(a[2]), "r"(a[3]), "r"(b0), "r"(b1));
}

// issue 8 LDG.128 for this thread's slice of a [128][64] f32 tile
DEVINL void ldg_tile(const float* __restrict__ g, float4* r, int row, int c0) {
    const float* gp = g + (size_t)row * Dd;
#pragma unroll
    for (int i = 0; i < 4; ++i) {
        r[2 * i]     = *reinterpret_cast<const float4*>(gp + c0 + 8 * i);
        r[2 * i + 1] = *reinterpret_cast<const float4*>(gp + c0 + 8 * i + 4);
    }
}
// convert this thread's slice to bf16 hi/lo and store swizzled
DEVINL void cvt_store(const float4* r, char* hi, char* lo, int row, int c0) {
#pragma unroll
    for (int i = 0; i < 4; ++i) {
        float4 a = r[2 * i], b = r[2 * i + 1];
        uint4 H = make_uint4(pack_hi(a.x, a.y), pack_hi(a.z, a.w),
                             pack_hi(b.x, b.y), pack_hi(b.z, b.w));
        uint4 Lo = make_uint4(pack_lo(a.x, a.y), pack_lo(a.z, a.w),
                              pack_lo(b.x, b.y), pack_lo(b.z, b.w));
        u32 off = swz((u32)(row * 128 + (c0 + 8 * i) * 2));
        *reinterpret_cast<uint4*>(hi + off) = H;
        *reinterpret_cast<uint4*>(lo + off) = Lo;
    }
}

// fp32 [128][64] gmem tile -> bf16 hi/lo smem (used for Q staging & tile 0)
template <bool SC>
DEVINL void load_split(const float* __restrict__ g, char* hi, char* lo, int row, int c0) {
    float4 r[8];
    ldg_tile(g, r, row, c0);
    if (SC) {
#pragma unroll
        for (int i = 0; i < 8; ++i) {
            r[i].x *= QSCALE; r[i].y *= QSCALE; r[i].z *= QSCALE; r[i].w *= QSCALE;
        }
    }
    cvt_store(r, hi, lo, row, c0);
}

__global__ void __launch_bounds__(NT, 1)
attn_mma(const float* __restrict__ Q, const float* __restrict__ K,
         const float* __restrict__ V, const float* __restrict__ QM,
         const float* __restrict__ KM, float* __restrict__ Out)
{
    extern __shared__ char sm[];
    const u32 smb = smem_u32(sm);
    const int tid = threadIdx.x, w = tid >> 5, L = tid & 31;
    const int b = blockIdx.y, q0 = blockIdx.x * TQ;
    const int prow = tid >> 1, pc0 = (tid & 1) * 32;   // per-thread load slice

    const float* Qb = Q + (size_t)(b * Ll + q0) * Dd;
    const float* Kb = K + (size_t)b * Ll * Dd;
    const float* Vb = V + (size_t)b * Ll * Dd;

    // ---- stage Q (scaled) through buf0 K slots, build resident A fragments ----
    load_split<true>(Qb, sm + OF_KH, sm + OF_KL, prow, pc0);
    __syncthreads();

    const int m = L >> 3;
    const u32 xm = (u32)(L & 7) << 4;
    const int arw = (m & 1) * 8 + (L & 7);
    const u32 acolsel = (u32)(m >> 1) * 16;
    u32 qh[4][4], ql[4][4];
#pragma unroll
    for (int kc = 0; kc < 4; ++kc) {
        u32 off = (u32)(16 * w + arw) * 128 + (((u32)kc * 32 + acolsel) ^ xm);
        ldsm4(qh[kc], smb + OF_KH + off);
        ldsm4(ql[kc], smb + OF_KL + off);
    }
    __syncthreads();   // everyone done reading Q before tile 0 overwrites

    // ---- tile 0 into buf0 ----
    load_split<false>(Kb, sm + OF_KH, sm + OF_KL, prow, pc0);
    load_split<false>(Vb, sm + OF_VH, sm + OF_VL, prow, pc0);
    if (tid < 128)
        reinterpret_cast<float*>(sm + SM_KM)[tid] = KM[b * Ll + tid];
    __syncthreads();

    const u32 krw_off = (u32)((m >> 1) * 8 + (L & 7)) * 128;
    const u32 kcolsel = (u32)(m & 1) * 16;
    const u32 vrw_off = (u32)arw * 128;
    const u32 vcolsel = (u32)(m >> 1) * 16;

    float oacc[8][4];
#pragma unroll
    for (int j = 0; j < 8; ++j) { oacc[j][0] = 0; oacc[j][1] = 0; oacc[j][2] = 0; oacc[j][3] = 0; }
    float rs0 = 0.f, rs1 = 0.f;

    for (int kt = 0; kt < NTILES; ++kt) {
        const int cur = kt & 1, alt = cur ^ 1;
        char* ba = sm + alt * 65536;
        const u32 smc = smb + (u32)cur * 65536;
        const bool pf = (kt + 1 < NTILES);

        // prefetch K(kt+1): LDGs in flight during GEMM1
        float4 kp[8];
        if (pf) ldg_tile(Kb + (size_t)(kt + 1) * 128 * Dd, kp, prow, pc0);

        // ---- GEMM1: S = Q @ K^T  (bf16x3) ----
        float sacc[16][4];
#pragma unroll
        for (int j = 0; j < 16; ++j) { sacc[j][0] = 0; sacc[j][1] = 0; sacc[j][2] = 0; sacc[j][3] = 0; }
#pragma unroll
        for (int j2 = 0; j2 < 8; ++j2) {
            u32 base = smc + (u32)j2 * 2048 + krw_off;
#pragma unroll
            for (int kc = 0; kc < 4; ++kc) {
                u32 coff = (((u32)kc * 32 + kcolsel) ^ xm);
                u32 bh[4], bl[4];
                ldsm4(bh, base + OF_KH + coff);
                ldsm4(bl, base + OF_KL + coff);
                mma16816(sacc[2 * j2],     qh[kc], bh[0], bh[1]);
                mma16816(sacc[2 * j2],     ql[kc], bh[0], bh[1]);
                mma16816(sacc[2 * j2],     qh[kc], bl[0], bl[1]);
                mma16816(sacc[2 * j2 + 1], qh[kc], bh[2], bh[3]);
                mma16816(sacc[2 * j2 + 1], ql[kc], bh[2], bh[3]);
                mma16816(sacc[2 * j2 + 1], qh[kc], bl[2], bl[3]);
            }
        }
        if (pf) cvt_store(kp, ba + OF_KH, ba + OF_KL, prow, pc0);

        // prefetch V(kt+1): LDGs in flight during softmax + GEMM2
        float4 vp[8];
        float kmn = 0.f;
        if (pf) {
            ldg_tile(Vb + (size_t)(kt + 1) * 128 * Dd, vp, prow, pc0);
            if (tid < 128) kmn = KM[b * Ll + (kt + 1) * 128 + tid];
        }

        // ---- fused softmax + GEMM2: O += P @ V  (P stays in registers) ----
        const float* kmp = reinterpret_cast<const float*>(sm + SM_KM) + cur * 128;
#pragma unroll
        for (int kc = 0; kc < 8; ++kc) {
            u32 Ah[4], Al[4];
#pragma unroll
            for (int half = 0; half < 2; ++half) {
                int j = 2 * kc + half;
                float2 km2 = *reinterpret_cast<const float2*>(kmp + 8 * j + 2 * (L & 3));
                float p0 = ex2f(sacc[j][0]) * km2.x;
                float p1 = ex2f(sacc[j][1]) * km2.y;
                float p2 = ex2f(sacc[j][2]) * km2.x;
                float p3 = ex2f(sacc[j][3]) * km2.y;
                rs0 += p0 + p1;
                rs1 += p2 + p3;
                Ah[2 * half]     = pack_hi(p0, p1);
                Ah[2 * half + 1] = pack_hi(p2, p3);
                Al[2 * half]     = pack_lo(p0, p1);
                Al[2 * half + 1] = pack_lo(p2, p3);
            }
            u32 base = smc + (u32)kc * 2048 + vrw_off;
#pragma unroll
            for (int j2 = 0; j2 < 4; ++j2) {
                u32 coff = (((u32)j2 * 32 + vcolsel) ^ xm);
                u32 vh[4], vl[4];
                ldsm4t(vh, base + OF_VH + coff);
                ldsm4t(vl, base + OF_VL + coff);
                mma16816(oacc[2 * j2],     Ah, vh[0], vh[1]);
                mma16816(oacc[2 * j2],     Al, vh[0], vh[1]);
                mma16816(oacc[2 * j2],     Ah, vl[0], vl[1]);
                mma16816(oacc[2 * j2 + 1], Ah, vh[2], vh[3]);
                mma16816(oacc[2 * j2 + 1], Al, vh[2], vh[3]);
                mma16816(oacc[2 * j2 + 1], Ah, vl[2], vl[3]);
            }
        }
        if (pf) {
            cvt_store(vp, ba + OF_VH, ba + OF_VL, prow, pc0);
            if (tid < 128)
                reinterpret_cast<float*>(sm + SM_KM)[alt * 128 + tid] = kmn;
        }
        __syncthreads();   // cur free for overwrite; alt writes visible
    }

    // ---- final: quad-reduce rowsums, divide, write ----
    rs0 += __shfl_xor_sync(0xFFFFFFFFu, rs0, 1);
    rs0 += __shfl_xor_sync(0xFFFFFFFFu, rs0, 2);
    rs1 += __shfl_xor_sync(0xFFFFFFFFu, rs1, 1);
    rs1 += __shfl_xor_sync(0xFFFFFFFFu, rs1, 2);

    int r0 = q0 + 16 * w + (L >> 2);
    int r1 = r0 + 8;
    float dv0 = QM[b * Ll + r0] / fmaxf(rs0, 2e-15f);
    float dv1 = QM[b * Ll + r1] / fmaxf(rs1, 2e-15f);

    float* o0 = Out + (size_t)(b * Ll + r0) * Dd + 2 * (L & 3);
    float* o1 = Out + (size_t)(b * Ll + r1) * Dd + 2 * (L & 3);
#pragma unroll
    for (int j = 0; j < 8; ++j) {
        *reinterpret_cast<float2*>(o0 + 8 * j) = make_float2(oacc[j][0] * dv0, oacc[j][1] * dv0);
        *reinterpret_cast<float2*>(o1 + 8 * j) = make_float2(oacc[j][2] * dv1, oacc[j][3] * dv1);
    }
}

extern "C" void kernel_launch(void* const* d_in, const int* in_sizes, int n_in,
                              void* d_out, int out_size) {
    const float* Q  = (const float*)d_in[0];
    const float* K  = (const float*)d_in[1];
    const float* V  = (const float*)d_in[2];
    const float* QM = (const float*)d_in[3];
    const float* KM = (const float*)d_in[4];
    float* Out = (float*)d_out;

    cudaFuncSetAttribute(attn_mma, cudaFuncAttributeMaxDynamicSharedMemorySize, SM_TOT);
    dim3 grid(Ll / TQ, Bb);   // 16 q-tiles x 8 batches = 128 CTAs
    attn_mma<<<grid, NT, SM_TOT>>>(Q, K, V, QM, KM, Out);
}

// round 6
// speedup vs baseline: 3.4140x; 1.2616x over previous
#include <cuda_runtime.h>

typedef unsigned int u32;
#define DEVINL __device__ __forceinline__

static constexpr int Bb = 8, Ll = 2048, Dd = 64;
static constexpr int TQ = 128, NT = 256, NTILES = 16;
static constexpr float QSCALE = 0.18033688011112042f; // log2(e)/8

// global scratch: pre-split, pre-swizzled bf16 tiles [b][tile][16384B]
__device__ __align__(16) unsigned char g_kh[Bb][16][16384];
__device__ __align__(16) unsigned char g_kl[Bb][16][16384];
__device__ __align__(16) unsigned char g_vh[Bb][16][16384];
__device__ __align__(16) unsigned char g_vl[Bb][16][16384];
__device__ __align__(16) unsigned char g_qh[Bb][16][16384];
__device__ __align__(16) unsigned char g_ql[Bb][16][16384];

// smem: two KV buffers + persistent Q + km
static constexpr int OF_KH = 0;        // within a KV buffer
static constexpr int OF_KL = 16384;
static constexpr int OF_VH = 32768;
static constexpr int OF_VL = 49152;
static constexpr int SM_QH = 131072;
static constexpr int SM_QL = 147456;
static constexpr int SM_KM = 163840;   // km[2][128] f32
static constexpr int SM_TOT = 164864;

DEVINL u32 smem_u32(const void* p) {
    u32 a;
    asm("{ .reg .u64 t; cvta.to.shared.u64 t, %1; cvt.u32.u64 %0, t; }" : "=r"(a) : "l"(p));
    return a;
}
DEVINL u32 swz(u32 o) { return o ^ ((o >> 3) & 0x70); }
DEVINL float ex2f(float x) { float r; asm("ex2.approx.f32 %0, %1;" : "=f"(r) : "f"(x)); return r; }

DEVINL u32 pack_hi(float a, float b) {
    return __byte_perm(__float_as_uint(a), __float_as_uint(b), 0x7632);
}
DEVINL u32 pack_lo(float a, float b) {
    float la = a - __uint_as_float(__float_as_uint(a) & 0xFFFF0000u);
    float lb = b - __uint_as_float(__float_as_uint(b) & 0xFFFF0000u);
    u32 r;
    asm("cvt.rn.satfinite.bf16x2.f32 %0, %1, %2;" : "=r"(r) : "f"(lb), "f"(la));
    return r;
}

DEVINL void ldsm4(u32* r, u32 a) {
    asm volatile("ldmatrix.sync.aligned.m8n8.x4.shared.b16 {%0,%1,%2,%3}, [%4];"
                 : "=r"(r[0]), "=r"(r[1]), "=r"(r[2]), "=r"(r[3]) : "r"(a) : "memory");
}
DEVINL void ldsm4t(u32* r, u32 a) {
    asm volatile("ldmatrix.sync.aligned.m8n8.x4.trans.shared.b16 {%0,%1,%2,%3}, [%4];"
                 : "=r"(r[0]), "=r"(r[1]), "=r"(r[2]), "=r"(r[3]) : "r"(a) : "memory");
}
DEVINL void mma16816(float* c, const u32* a, u32 b0, u32 b1) {
    asm("mma.sync.aligned.m16n8k16.row.col.f32.bf16.bf16.f32 "
        "{%0,%1,%2,%3}, {%4,%5,%6,%7}, {%8,%9}, {%0,%1,%2,%3};"
        : "+f"(c[0]), "+f"(c[1]), "+f"(c[2]), "+f"(c[3])
        : "r"(a[0]), "r"(a[1]), "r"(a[2]), "r"(a[3]), "r"(b0), "r"(b1));
}

DEVINL void cpa16(u32 dst, const void* src) {
    asm volatile("cp.async.cg.shared.global [%0], [%1], 16;" :: "r"(dst), "l"(src) : "memory");
}
DEVINL void cpa_commit() { asm volatile("cp.async.commit_group;" ::: "memory"); }
DEVINL void cpa_wait0()  { asm volatile("cp.async.wait_group 0;" ::: "memory"); }

// ---------------- kernel 1: fp32 -> bf16 hi/lo, tile-swizzled ----------------
__global__ void __launch_bounds__(256, 4)
presplit(const float* __restrict__ Q, const float* __restrict__ K,
         const float* __restrict__ V)
{
    int tensor = blockIdx.y;                       // 0=K, 1=V, 2=Q
    int c = blockIdx.x * 256 + threadIdx.x;        // chunk id, 8 floats each
    int b  = c >> 14;                              // 16384 chunks per batch
    int l  = (c >> 3) & 2047;
    int d0 = (c & 7) * 8;

    const float* src = (tensor == 0 ? K : tensor == 1 ? V : Q)
                       + ((size_t)(b * Ll + l) * Dd + d0);
    float4 a = *reinterpret_cast<const float4*>(src);
    float4 e = *reinterpret_cast<const float4*>(src + 4);
    if (tensor == 2) {
        a.x *= QSCALE; a.y *= QSCALE; a.z *= QSCALE; a.w *= QSCALE;
        e.x *= QSCALE; e.y *= QSCALE; e.z *= QSCALE; e.w *= QSCALE;
    }
    uint4 H = make_uint4(pack_hi(a.x, a.y), pack_hi(a.z, a.w),
                         pack_hi(e.x, e.y), pack_hi(e.z, e.w));
    uint4 Lo = make_uint4(pack_lo(a.x, a.y), pack_lo(a.z, a.w),
                          pack_lo(e.x, e.y), pack_lo(e.z, e.w));
    int tile = l >> 7, row = l & 127;
    u32 off = swz((u32)(row * 128 + d0 * 2));
    unsigned char* oh = (tensor == 0 ? g_kh : tensor == 1 ? g_vh : g_qh)[b][tile];
    unsigned char* ol = (tensor == 0 ? g_kl : tensor == 1 ? g_vl : g_ql)[b][tile];
    *reinterpret_cast<uint4*>(oh + off) = H;
    *reinterpret_cast<uint4*>(ol + off) = Lo;
}

// ---------------- kernel 2: attention ----------------
__global__ void __launch_bounds__(NT, 1)
attn_mma(const float* __restrict__ QM, const float* __restrict__ KM,
         float* __restrict__ Out)
{
    extern __shared__ char sm[];
    const u32 smb = smem_u32(sm);
    const int tid = threadIdx.x, w = tid >> 5, L = tid & 31;
    const int b = blockIdx.y, qt = blockIdx.x, q0 = qt * TQ;
    const int mg = w >> 1, kh = w & 1;             // M-group, key-half

    // issue Q tile (persistent) + tile 0 KV + km0
    {
#pragma unroll
        for (int t = 0; t < 4; ++t) {
            u32 o = (u32)(tid + 256 * t) * 16;
            cpa16(smb + SM_QH + o, g_qh[b][qt] + o);
            cpa16(smb + SM_QL + o, g_ql[b][qt] + o);
            cpa16(smb + OF_KH + o, g_kh[b][0] + o);
            cpa16(smb + OF_KL + o, g_kl[b][0] + o);
            cpa16(smb + OF_VH + o, g_vh[b][0] + o);
            cpa16(smb + OF_VL + o, g_vl[b][0] + o);
        }
        if (tid < 32) cpa16(smb + SM_KM + tid * 16, KM + b * Ll + tid * 4);
        cpa_commit();
        cpa_wait0();
        __syncthreads();
    }

    // lane addressing (same verified ldmatrix patterns)
    const int m = L >> 3;
    const u32 xm = (u32)(L & 7) << 4;
    const int arw = (m & 1) * 8 + (L & 7);
    const u32 acolsel = (u32)(m >> 1) * 16;
    const u32 krw_off = (u32)((m >> 1) * 8 + (L & 7)) * 128;
    const u32 kcolsel = (u32)(m & 1) * 16;
    const u32 vrw_off = (u32)arw * 128;
    const u32 vcolsel = (u32)(m >> 1) * 16;
    const u32 khrow = (u32)(kh * 64);              // this warp's key base row

    float oacc[2][8][4];
#pragma unroll
    for (int mt = 0; mt < 2; ++mt)
#pragma unroll
        for (int j = 0; j < 8; ++j)
            { oacc[mt][j][0] = 0; oacc[mt][j][1] = 0; oacc[mt][j][2] = 0; oacc[mt][j][3] = 0; }
    float rs[2][2] = {{0.f, 0.f}, {0.f, 0.f}};

    for (int kt = 0; kt < NTILES; ++kt) {
        const int cur = kt & 1;
        const u32 smc = smb + (u32)cur * 65536;
        const bool pf = (kt + 1 < NTILES);
        if (pf) {
            const u32 sma = smb + (u32)(cur ^ 1) * 65536;
            const int nt2 = kt + 1;
#pragma unroll
            for (int t = 0; t < 4; ++t) {
                u32 o = (u32)(tid + 256 * t) * 16;
                cpa16(sma + OF_KH + o, g_kh[b][nt2] + o);
                cpa16(sma + OF_KL + o, g_kl[b][nt2] + o);
                cpa16(sma + OF_VH + o, g_vh[b][nt2] + o);
                cpa16(sma + OF_VL + o, g_vl[b][nt2] + o);
            }
            if (tid < 32)
                cpa16(smb + SM_KM + (u32)(cur ^ 1) * 512 + tid * 16,
                      KM + b * Ll + nt2 * 128 + tid * 4);
            cpa_commit();
        }

        // ---- GEMM1: S[32 rows][64 keys] = Q @ K^T (bf16x3), kc-outer ----
        float sacc[2][8][4];
#pragma unroll
        for (int mt = 0; mt < 2; ++mt)
#pragma unroll
            for (int j = 0; j < 8; ++j)
                { sacc[mt][j][0] = 0; sacc[mt][j][1] = 0; sacc[mt][j][2] = 0; sacc[mt][j][3] = 0; }
#pragma unroll
        for (int kc = 0; kc < 4; ++kc) {
            u32 qcoff = (((u32)kc * 32 + acolsel) ^ xm);
            u32 qh0[4], ql0[4], qh1[4], ql1[4];
            u32 qa0 = (u32)(mg * 32 + arw) * 128 + qcoff;
            u32 qa1 = (u32)(mg * 32 + 16 + arw) * 128 + qcoff;
            ldsm4(qh0, smb + SM_QH + qa0);
            ldsm4(ql0, smb + SM_QL + qa0);
            ldsm4(qh1, smb + SM_QH + qa1);
            ldsm4(ql1, smb + SM_QL + qa1);
            u32 coff = (((u32)kc * 32 + kcolsel) ^ xm);
#pragma unroll
            for (int j2 = 0; j2 < 4; ++j2) {
                u32 base = smc + (khrow + (u32)j2 * 16) * 128 + krw_off + coff;
                u32 bh[4], bl[4];
                ldsm4(bh, base + OF_KH);
                ldsm4(bl, base + OF_KL);
                mma16816(sacc[0][2 * j2],     qh0, bh[0], bh[1]);
                mma16816(sacc[0][2 * j2],     ql0, bh[0], bh[1]);
                mma16816(sacc[0][2 * j2],     qh0, bl[0], bl[1]);
                mma16816(sacc[0][2 * j2 + 1], qh0, bh[2], bh[3]);
                mma16816(sacc[0][2 * j2 + 1], ql0, bh[2], bh[3]);
                mma16816(sacc[0][2 * j2 + 1], qh0, bl[2], bl[3]);
                mma16816(sacc[1][2 * j2],     qh1, bh[0], bh[1]);
                mma16816(sacc[1][2 * j2],     ql1, bh[0], bh[1]);
                mma16816(sacc[1][2 * j2],     qh1, bl[0], bl[1]);
                mma16816(sacc[1][2 * j2 + 1], qh1, bh[2], bh[3]);
                mma16816(sacc[1][2 * j2 + 1], ql1, bh[2], bh[3]);
                mma16816(sacc[1][2 * j2 + 1], qh1, bl[2], bl[3]);
            }
        }

        // ---- softmax + GEMM2: O += P @ V (P in registers) ----
        const float* kmp = reinterpret_cast<const float*>(sm + SM_KM) + cur * 128 + kh * 64;
#pragma unroll
        for (int kc = 0; kc < 4; ++kc) {
            u32 Ah[2][4], Al[2][4];
#pragma unroll
            for (int mt = 0; mt < 2; ++mt)
#pragma unroll
                for (int half = 0; half < 2; ++half) {
                    int j = 2 * kc + half;
                    float2 km2 = *reinterpret_cast<const float2*>(kmp + 8 * j + 2 * (L & 3));
                    float p0 = ex2f(sacc[mt][j][0]) * km2.x;
                    float p1 = ex2f(sacc[mt][j][1]) * km2.y;
                    float p2 = ex2f(sacc[mt][j][2]) * km2.x;
                    float p3 = ex2f(sacc[mt][j][3]) * km2.y;
                    rs[mt][0] += p0 + p1;
                    rs[mt][1] += p2 + p3;
                    Ah[mt][2 * half]     = pack_hi(p0, p1);
                    Ah[mt][2 * half + 1] = pack_hi(p2, p3);
                    Al[mt][2 * half]     = pack_lo(p0, p1);
                    Al[mt][2 * half + 1] = pack_lo(p2, p3);
                }
            u32 vbase = smc + (khrow + (u32)kc * 16) * 128 + vrw_off;
#pragma unroll
            for (int j2 = 0; j2 < 4; ++j2) {
                u32 coff = (((u32)j2 * 32 + vcolsel) ^ xm);
                u32 vh[4], vl[4];
                ldsm4t(vh, vbase + OF_VH + coff);
                ldsm4t(vl, vbase + OF_VL + coff);
#pragma unroll
                for (int mt = 0; mt < 2; ++mt) {
                    mma16816(oacc[mt][2 * j2],     Ah[mt], vh[0], vh[1]);
                    mma16816(oacc[mt][2 * j2],     Al[mt], vh[0], vh[1]);
                    mma16816(oacc[mt][2 * j2],     Ah[mt], vl[0], vl[1]);
                    mma16816(oacc[mt][2 * j2 + 1], Ah[mt], vh[2], vh[3]);
                    mma16816(oacc[mt][2 * j2 + 1], Al[mt], vh[2], vh[3]);
                    mma16816(oacc[mt][2 * j2 + 1], Ah[mt], vl[2], vl[3]);
                }
            }
        }

        if (pf) cpa_wait0();
        __syncthreads();   // next buffer ready; current buffer free
    }

    // ---- epilogue: quad-reduce rowsums, cross-warp (key-half) combine ----
#pragma unroll
    for (int mt = 0; mt < 2; ++mt)
#pragma unroll
        for (int s = 0; s < 2; ++s) {
            rs[mt][s] += __shfl_xor_sync(0xFFFFFFFFu, rs[mt][s], 1);
            rs[mt][s] += __shfl_xor_sync(0xFFFFFFFFu, rs[mt][s], 2);
        }

    float* OS = reinterpret_cast<float*>(sm);            // [128][64] (buf0 KH/KL)
    float* RS = reinterpret_cast<float*>(sm + 32768);    // [128] (buf0 VH)
    if (kh == 1) {
#pragma unroll
        for (int mt = 0; mt < 2; ++mt) {
            int ra = mg * 32 + mt * 16 + (L >> 2);
            int rb = ra + 8;
#pragma unroll
            for (int j = 0; j < 8; ++j) {
                *reinterpret_cast<float2*>(&OS[ra * 64 + 8 * j + 2 * (L & 3)]) =
                    make_float2(oacc[mt][j][0], oacc[mt][j][1]);
                *reinterpret_cast<float2*>(&OS[rb * 64 + 8 * j + 2 * (L & 3)]) =
                    make_float2(oacc[mt][j][2], oacc[mt][j][3]);
            }
            if ((L & 3) == 0) { RS[ra] = rs[mt][0]; RS[rb] = rs[mt][1]; }
        }
    }
    __syncthreads();
    if (kh == 0) {
#pragma unroll
        for (int mt = 0; mt < 2; ++mt) {
            int ra = mg * 32 + mt * 16 + (L >> 2);
            int rb = ra + 8;
            float sa = rs[mt][0] + RS[ra];
            float sb = rs[mt][1] + RS[rb];
            float dva = QM[b * Ll + q0 + ra] / fmaxf(sa, 2e-15f);
            float dvb = QM[b * Ll + q0 + rb] / fmaxf(sb, 2e-15f);
            float* oa = Out + (size_t)(b * Ll + q0 + ra) * Dd + 2 * (L & 3);
            float* ob = Out + (size_t)(b * Ll + q0 + rb) * Dd + 2 * (L & 3);
#pragma unroll
            for (int j = 0; j < 8; ++j) {
                float2 ua = *reinterpret_cast<const float2*>(&OS[ra * 64 + 8 * j + 2 * (L & 3)]);
                float2 ub = *reinterpret_cast<const float2*>(&OS[rb * 64 + 8 * j + 2 * (L & 3)]);
                *reinterpret_cast<float2*>(oa + 8 * j) =
                    make_float2((oacc[mt][j][0] + ua.x) * dva, (oacc[mt][j][1] + ua.y) * dva);
                *reinterpret_cast<float2*>(ob + 8 * j) =
                    make_float2((oacc[mt][j][2] + ub.x) * dvb, (oacc[mt][j][3] + ub.y) * dvb);
            }
        }
    }
}

extern "C" void kernel_launch(void* const* d_in, const int* in_sizes, int n_in,
                              void* d_out, int out_size) {
    const float* Q  = (const float*)d_in[0];
    const float* K  = (const float*)d_in[1];
    const float* V  = (const float*)d_in[2];
    const float* QM = (const float*)d_in[3];
    const float* KM = (const float*)d_in[4];
    float* Out = (float*)d_out;

    presplit<<<dim3(512, 3), 256>>>(Q, K, V);

    cudaFuncSetAttribute(attn_mma, cudaFuncAttributeMaxDynamicSharedMemorySize, SM_TOT);
    dim3 grid(Ll / TQ, Bb);   // 16 q-tiles x 8 batches = 128 CTAs
    attn_mma<<<grid, NT, SM_TOT>>>(QM, KM, Out);
}

// round 7
// speedup vs baseline: 4.5928x; 1.3453x over previous
#include <cuda_runtime.h>
#include <cuda_fp16.h>

typedef unsigned int u32;
#define DEVINL __device__ __forceinline__

static constexpr int Bb = 8, Ll = 2048, Dd = 64;
static constexpr int TQ = 128, NT = 256, NTILES = 16;
static constexpr float QSCALE = 0.18033688011112042f; // log2(e)/8

// global scratch: pre-split, pre-swizzled fp16 tiles [b][tile][16384B]
__device__ __align__(16) unsigned char g_kh[Bb][16][16384];
__device__ __align__(16) unsigned char g_kl[Bb][16][16384];
__device__ __align__(16) unsigned char g_vh[Bb][16][16384];
__device__ __align__(16) unsigned char g_qh[Bb][16][16384];
__device__ __align__(16) unsigned char g_ql[Bb][16][16384];

// smem: two KV buffers (KH,KL,VH) + persistent Q(H,L) + km
static constexpr int OF_KH = 0;
static constexpr int OF_KL = 16384;
static constexpr int OF_VH = 32768;
static constexpr int BUFSZ = 49152;
static constexpr int SM_QH = 98304;
static constexpr int SM_QL = 114688;
static constexpr int SM_KM = 131072;   // km[2][128] f32
static constexpr int SM_TOT = 132096;

DEVINL u32 smem_u32(const void* p) {
    u32 a;
    asm("{ .reg .u64 t; cvta.to.shared.u64 t, %1; cvt.u32.u64 %0, t; }" : "=r"(a) : "l"(p));
    return a;
}
DEVINL u32 swz(u32 o) { return o ^ ((o >> 3) & 0x70); }
DEVINL float ex2f(float x) { float r; asm("ex2.approx.f32 %0, %1;" : "=f"(r) : "f"(x)); return r; }

// pack two f32 -> f16x2 (lo in low half)
DEVINL u32 packh2(float lo, float hi) {
    u32 r; asm("cvt.rn.f16x2.f32 %0, %1, %2;" : "=r"(r) : "f"(hi), "f"(lo)); return r;
}
// fp16 hi/lo split of (a,b): H packed hi pair, Lo packed residual pair
DEVINL void split_h2(float a, float b, u32& H, u32& Lo) {
    __half ha = __float2half_rn(a), hb = __float2half_rn(b);
    float ra = a - __half2float(ha), rb = b - __half2float(hb);
    H = ((u32)__half_as_ushort(hb) << 16) | (u32)__half_as_ushort(ha);
    Lo = packh2(ra, rb);
}

DEVINL void ldsm4(u32* r, u32 a) {
    asm volatile("ldmatrix.sync.aligned.m8n8.x4.shared.b16 {%0,%1,%2,%3}, [%4];"
                 : "=r"(r[0]), "=r"(r[1]), "=r"(r[2]), "=r"(r[3]) : "r"(a) : "memory");
}
DEVINL void ldsm4t(u32* r, u32 a) {
    asm volatile("ldmatrix.sync.aligned.m8n8.x4.trans.shared.b16 {%0,%1,%2,%3}, [%4];"
                 : "=r"(r[0]), "=r"(r[1]), "=r"(r[2]), "=r"(r[3]) : "r"(a) : "memory");
}
DEVINL void mma16816(float* c, const u32* a, u32 b0, u32 b1) {
    asm("mma.sync.aligned.m16n8k16.row.col.f32.f16.f16.f32 "
        "{%0,%1,%2,%3}, {%4,%5,%6,%7}, {%8,%9}, {%0,%1,%2,%3};"
        : "+f"(c[0]), "+f"(c[1]), "+f"(c[2]), "+f"(c[3])
        : "r"(a[0]), "r"(a[1]), "r"(a[2]), "r"(a[3]), "r"(b0), "r"(b1));
}

DEVINL void cpa16(u32 dst, const void* src) {
    asm volatile("cp.async.cg.shared.global [%0], [%1], 16;" :: "r"(dst), "l"(src) : "memory");
}
DEVINL void cpa_commit() { asm volatile("cp.async.commit_group;" ::: "memory"); }
DEVINL void cpa_wait0()  { asm volatile("cp.async.wait_group 0;" ::: "memory"); }

// ---------------- kernel 1: fp32 -> fp16 hi/lo, tile-swizzled ----------------
__global__ void __launch_bounds__(256, 4)
presplit(const float* __restrict__ Q, const float* __restrict__ K,
         const float* __restrict__ V)
{
    int tensor = blockIdx.y;                       // 0=K(h,l), 1=V(h), 2=Q(h,l)
    int c = blockIdx.x * 256 + threadIdx.x;
    int b  = c >> 14;
    int l  = (c >> 3) & 2047;
    int d0 = (c & 7) * 8;

    const float* src = (tensor == 0 ? K : tensor == 1 ? V : Q)
                       + ((size_t)(b * Ll + l) * Dd + d0);
    float4 a = *reinterpret_cast<const float4*>(src);
    float4 e = *reinterpret_cast<const float4*>(src + 4);
    if (tensor == 2) {
        a.x *= QSCALE; a.y *= QSCALE; a.z *= QSCALE; a.w *= QSCALE;
        e.x *= QSCALE; e.y *= QSCALE; e.z *= QSCALE; e.w *= QSCALE;
    }
    uint4 H, Lo;
    split_h2(a.x, a.y, H.x, Lo.x);
    split_h2(a.z, a.w, H.y, Lo.y);
    split_h2(e.x, e.y, H.z, Lo.z);
    split_h2(e.z, e.w, H.w, Lo.w);

    int tile = l >> 7, row = l & 127;
    u32 off = swz((u32)(row * 128 + d0 * 2));
    unsigned char* oh = (tensor == 0 ? g_kh : tensor == 1 ? g_vh : g_qh)[b][tile];
    *reinterpret_cast<uint4*>(oh + off) = H;
    if (tensor != 1) {
        unsigned char* ol = (tensor == 0 ? g_kl : g_ql)[b][tile];
        *reinterpret_cast<uint4*>(ol + off) = Lo;
    }
}

// ---------------- kernel 2: attention ----------------
__global__ void __launch_bounds__(NT, 1)
attn_mma(const float* __restrict__ QM, const float* __restrict__ KM,
         float* __restrict__ Out)
{
    extern __shared__ char sm[];
    const u32 smb = smem_u32(sm);
    const int tid = threadIdx.x, w = tid >> 5, L = tid & 31;
    const int b = blockIdx.y, qt = blockIdx.x, q0 = qt * TQ;
    const int mg = w >> 1, kh = w & 1;

    // issue Q (persistent) + tile 0 KV + km0
    {
#pragma unroll
        for (int t = 0; t < 4; ++t) {
            u32 o = (u32)(tid + 256 * t) * 16;
            cpa16(smb + SM_QH + o, g_qh[b][qt] + o);
            cpa16(smb + SM_QL + o, g_ql[b][qt] + o);
            cpa16(smb + OF_KH + o, g_kh[b][0] + o);
            cpa16(smb + OF_KL + o, g_kl[b][0] + o);
            cpa16(smb + OF_VH + o, g_vh[b][0] + o);
        }
        if (tid < 32) cpa16(smb + SM_KM + tid * 16, KM + b * Ll + tid * 4);
        cpa_commit();
        cpa_wait0();
        __syncthreads();
    }

    const int m = L >> 3;
    const u32 xm = (u32)(L & 7) << 4;
    const int arw = (m & 1) * 8 + (L & 7);
    const u32 acolsel = (u32)(m >> 1) * 16;
    const u32 krw_off = (u32)((m >> 1) * 8 + (L & 7)) * 128;
    const u32 kcolsel = (u32)(m & 1) * 16;
    const u32 vrw_off = (u32)arw * 128;
    const u32 vcolsel = (u32)(m >> 1) * 16;
    const u32 khrow = (u32)(kh * 64);

    float oacc[2][8][4];
#pragma unroll
    for (int mt = 0; mt < 2; ++mt)
#pragma unroll
        for (int j = 0; j < 8; ++j)
            { oacc[mt][j][0] = 0; oacc[mt][j][1] = 0; oacc[mt][j][2] = 0; oacc[mt][j][3] = 0; }
    float rs[2][2] = {{0.f, 0.f}, {0.f, 0.f}};

    for (int kt = 0; kt < NTILES; ++kt) {
        const int cur = kt & 1;
        const u32 smc = smb + (u32)cur * BUFSZ;
        const bool pf = (kt + 1 < NTILES);
        if (pf) {
            const u32 sma = smb + (u32)(cur ^ 1) * BUFSZ;
            const int nt2 = kt + 1;
#pragma unroll
            for (int t = 0; t < 4; ++t) {
                u32 o = (u32)(tid + 256 * t) * 16;
                cpa16(sma + OF_KH + o, g_kh[b][nt2] + o);
                cpa16(sma + OF_KL + o, g_kl[b][nt2] + o);
                cpa16(sma + OF_VH + o, g_vh[b][nt2] + o);
            }
            if (tid < 32)
                cpa16(smb + SM_KM + (u32)(cur ^ 1) * 512 + tid * 16,
                      KM + b * Ll + nt2 * 128 + tid * 4);
            cpa_commit();
        }

        // ---- GEMM1: S[32 rows][64 keys] = Q @ K^T (fp16 x3, acc-interleaved) ----
        float sacc[2][8][4];
#pragma unroll
        for (int mt = 0; mt < 2; ++mt)
#pragma unroll
            for (int j = 0; j < 8; ++j)
                { sacc[mt][j][0] = 0; sacc[mt][j][1] = 0; sacc[mt][j][2] = 0; sacc[mt][j][3] = 0; }
#pragma unroll
        for (int kc = 0; kc < 4; ++kc) {
            u32 qcoff = (((u32)kc * 32 + acolsel) ^ xm);
            u32 qh0[4], ql0[4], qh1[4], ql1[4];
            u32 qa0 = (u32)(mg * 32 + arw) * 128 + qcoff;
            u32 qa1 = (u32)(mg * 32 + 16 + arw) * 128 + qcoff;
            ldsm4(qh0, smb + SM_QH + qa0);
            ldsm4(ql0, smb + SM_QL + qa0);
            ldsm4(qh1, smb + SM_QH + qa1);
            ldsm4(ql1, smb + SM_QL + qa1);
            u32 coff = (((u32)kc * 32 + kcolsel) ^ xm);
#pragma unroll
            for (int j2 = 0; j2 < 4; ++j2) {
                u32 base = smc + (khrow + (u32)j2 * 16) * 128 + krw_off + coff;
                u32 bh[4], bl[4];
                ldsm4(bh, base + OF_KH);
                ldsm4(bl, base + OF_KL);
                // round-robin over 4 accumulators: dependent distance = 4
                mma16816(sacc[0][2 * j2],     qh0, bh[0], bh[1]);
                mma16816(sacc[0][2 * j2 + 1], qh0, bh[2], bh[3]);
                mma16816(sacc[1][2 * j2],     qh1, bh[0], bh[1]);
                mma16816(sacc[1][2 * j2 + 1], qh1, bh[2], bh[3]);
                mma16816(sacc[0][2 * j2],     ql0, bh[0], bh[1]);
                mma16816(sacc[0][2 * j2 + 1], ql0, bh[2], bh[3]);
                mma16816(sacc[1][2 * j2],     ql1, bh[0], bh[1]);
                mma16816(sacc[1][2 * j2 + 1], ql1, bh[2], bh[3]);
                mma16816(sacc[0][2 * j2],     qh0, bl[0], bl[1]);
                mma16816(sacc[0][2 * j2 + 1], qh0, bl[2], bl[3]);
                mma16816(sacc[1][2 * j2],     qh1, bl[0], bl[1]);
                mma16816(sacc[1][2 * j2 + 1], qh1, bl[2], bl[3]);
            }
        }

        // ---- softmax + GEMM2: O += P @ V (fp16 single-pass, P in registers) ----
        const float* kmp = reinterpret_cast<const float*>(sm + SM_KM) + cur * 128 + kh * 64;
#pragma unroll
        for (int kc = 0; kc < 4; ++kc) {
            u32 Ah[2][4];
#pragma unroll
            for (int mt = 0; mt < 2; ++mt)
#pragma unroll
                for (int half = 0; half < 2; ++half) {
                    int j = 2 * kc + half;
                    float2 km2 = *reinterpret_cast<const float2*>(kmp + 8 * j + 2 * (L & 3));
                    float p0 = ex2f(sacc[mt][j][0]) * km2.x;
                    float p1 = ex2f(sacc[mt][j][1]) * km2.y;
                    float p2 = ex2f(sacc[mt][j][2]) * km2.x;
                    float p3 = ex2f(sacc[mt][j][3]) * km2.y;
                    rs[mt][0] += p0 + p1;
                    rs[mt][1] += p2 + p3;
                    Ah[mt][2 * half]     = packh2(p0, p1);
                    Ah[mt][2 * half + 1] = packh2(p2, p3);
                }
            u32 vbase = smc + (khrow + (u32)kc * 16) * 128 + vrw_off;
#pragma unroll
            for (int j2 = 0; j2 < 4; ++j2) {
                u32 coff = (((u32)j2 * 32 + vcolsel) ^ xm);
                u32 vh[4];
                ldsm4t(vh, vbase + OF_VH + coff);
                mma16816(oacc[0][2 * j2],     Ah[0], vh[0], vh[1]);
                mma16816(oacc[0][2 * j2 + 1], Ah[0], vh[2], vh[3]);
                mma16816(oacc[1][2 * j2],     Ah[1], vh[0], vh[1]);
                mma16816(oacc[1][2 * j2 + 1], Ah[1], vh[2], vh[3]);
            }
        }

        if (pf) cpa_wait0();
        __syncthreads();
    }

    // ---- epilogue: quad-reduce rowsums, cross-warp (key-half) combine ----
#pragma unroll
    for (int mt = 0; mt < 2; ++mt)
#pragma unroll
        for (int s = 0; s < 2; ++s) {
            rs[mt][s] += __shfl_xor_sync(0xFFFFFFFFu, rs[mt][s], 1);
            rs[mt][s] += __shfl_xor_sync(0xFFFFFFFFu, rs[mt][s], 2);
        }

    float* OS = reinterpret_cast<float*>(sm);            // [128][64] f32 (buf0)
    float* RS = reinterpret_cast<float*>(sm + 32768);    // [128]
    if (kh == 1) {
#pragma unroll
        for (int mt = 0; mt < 2; ++mt) {
            int ra = mg * 32 + mt * 16 + (L >> 2);
            int rb = ra + 8;
#pragma unroll
            for (int j = 0; j < 8; ++j) {
                *reinterpret_cast<float2*>(&OS[ra * 64 + 8 * j + 2 * (L & 3)]) =
                    make_float2(oacc[mt][j][0], oacc[mt][j][1]);
                *reinterpret_cast<float2*>(&OS[rb * 64 + 8 * j + 2 * (L & 3)]) =
                    make_float2(oacc[mt][j][2], oacc[mt][j][3]);
            }
            if ((L & 3) == 0) { RS[ra] = rs[mt][0]; RS[rb] = rs[mt][1]; }
        }
    }
    __syncthreads();
    if (kh == 0) {
#pragma unroll
        for (int mt = 0; mt < 2; ++mt) {
            int ra = mg * 32 + mt * 16 + (L >> 2);
            int rb = ra + 8;
            float sa = rs[mt][0] + RS[ra];
            float sb = rs[mt][1] + RS[rb];
            float dva = QM[b * Ll + q0 + ra] / fmaxf(sa, 2e-15f);
            float dvb = QM[b * Ll + q0 + rb] / fmaxf(sb, 2e-15f);
            float* oa = Out + (size_t)(b * Ll + q0 + ra) * Dd + 2 * (L & 3);
            float* ob = Out + (size_t)(b * Ll + q0 + rb) * Dd + 2 * (L & 3);
#pragma unroll
            for (int j = 0; j < 8; ++j) {
                float2 ua = *reinterpret_cast<const float2*>(&OS[ra * 64 + 8 * j + 2 * (L & 3)]);
                float2 ub = *reinterpret_cast<const float2*>(&OS[rb * 64 + 8 * j + 2 * (L & 3)]);
                *reinterpret_cast<float2*>(oa + 8 * j) =
                    make_float2((oacc[mt][j][0] + ua.x) * dva, (oacc[mt][j][1] + ua.y) * dva);
                *reinterpret_cast<float2*>(ob + 8 * j) =
                    make_float2((oacc[mt][j][2] + ub.x) * dvb, (oacc[mt][j][3] + ub.y) * dvb);
            }
        }
    }
}

extern "C" void kernel_launch(void* const* d_in, const int* in_sizes, int n_in,
                              void* d_out, int out_size) {
    const float* Q  = (const float*)d_in[0];
    const float* K  = (const float*)d_in[1];
    const float* V  = (const float*)d_in[2];
    const float* QM = (const float*)d_in[3];
    const float* KM = (const float*)d_in[4];
    float* Out = (float*)d_out;

    presplit<<<dim3(512, 3), 256>>>(Q, K, V);

    cudaFuncSetAttribute(attn_mma, cudaFuncAttributeMaxDynamicSharedMemorySize, SM_TOT);
    dim3 grid(Ll / TQ, Bb);   // 16 q-tiles x 8 batches = 128 CTAs
    attn_mma<<<grid, NT, SM_TOT>>>(QM, KM, Out);
}

// round 8
// speedup vs baseline: 5.8419x; 1.2720x over previous
#include <cuda_runtime.h>
#include <cuda_fp16.h>

typedef unsigned int u32;
#define DEVINL __device__ __forceinline__

static constexpr int Bb = 8, Ll = 2048, Dd = 64;
static constexpr int TQ = 64, NT = 256, NTILES = 16;
static constexpr float QSCALE = 0.18033688011112042f; // log2(e)/8

// global scratch: fp16, tile-swizzled [b][tile of 128 rows][16384B]
__device__ __align__(16) unsigned char g_q[Bb][16][16384];
__device__ __align__(16) unsigned char g_k[Bb][16][16384];
__device__ __align__(16) unsigned char g_v[Bb][16][16384];

// smem: two KV buffers (K,V) + persistent Q + km
static constexpr int OF_K = 0;
static constexpr int OF_V = 16384;
static constexpr int BUFSZ = 32768;
static constexpr int SM_Q  = 65536;    // fp16 [64][64] = 8KB
static constexpr int SM_KM = 73728;    // km[2][128] f32 = 1KB
static constexpr int SM_TOT = 74752;

DEVINL u32 smem_u32(const void* p) {
    u32 a;
    asm("{ .reg .u64 t; cvta.to.shared.u64 t, %1; cvt.u32.u64 %0, t; }" : "=r"(a) : "l"(p));
    return a;
}
DEVINL u32 swz(u32 o) { return o ^ ((o >> 3) & 0x70); }
DEVINL float ex2f(float x) { float r; asm("ex2.approx.f32 %0, %1;" : "=f"(r) : "f"(x)); return r; }

// pack two f32 -> f16x2 (first arg in low half)
DEVINL u32 packh2(float lo, float hi) {
    u32 r; asm("cvt.rn.f16x2.f32 %0, %1, %2;" : "=r"(r) : "f"(hi), "f"(lo)); return r;
}

DEVINL void ldsm4(u32* r, u32 a) {
    asm volatile("ldmatrix.sync.aligned.m8n8.x4.shared.b16 {%0,%1,%2,%3}, [%4];"
                 : "=r"(r[0]), "=r"(r[1]), "=r"(r[2]), "=r"(r[3]) : "r"(a) : "memory");
}
DEVINL void ldsm4t(u32* r, u32 a) {
    asm volatile("ldmatrix.sync.aligned.m8n8.x4.trans.shared.b16 {%0,%1,%2,%3}, [%4];"
                 : "=r"(r[0]), "=r"(r[1]), "=r"(r[2]), "=r"(r[3]) : "r"(a) : "memory");
}
DEVINL void mma16816(float* c, const u32* a, u32 b0, u32 b1) {
    asm("mma.sync.aligned.m16n8k16.row.col.f32.f16.f16.f32 "
        "{%0,%1,%2,%3}, {%4,%5,%6,%7}, {%8,%9}, {%0,%1,%2,%3};"
        : "+f"(c[0]), "+f"(c[1]), "+f"(c[2]), "+f"(c[3])
        : "r"(a[0]), "r"(a[1]), "r"(a[2]), "r"(a[3]), "r"(b0), "r"(b1));
}

DEVINL void cpa16(u32 dst, const void* src) {
    asm volatile("cp.async.cg.shared.global [%0], [%1], 16;" :: "r"(dst), "l"(src) : "memory");
}
DEVINL void cpa_commit() { asm volatile("cp.async.commit_group;" ::: "memory"); }
DEVINL void cpa_wait0()  { asm volatile("cp.async.wait_group 0;" ::: "memory"); }

// ---------------- kernel 1: fp32 -> fp16, tile-swizzled ----------------
__global__ void __launch_bounds__(256, 4)
presplit(const float* __restrict__ Q, const float* __restrict__ K,
         const float* __restrict__ V)
{
    int tensor = blockIdx.y;                       // 0=K, 1=V, 2=Q(scaled)
    int c = blockIdx.x * 256 + threadIdx.x;
    int b  = c >> 14;
    int l  = (c >> 3) & 2047;
    int d0 = (c & 7) * 8;

    const float* src = (tensor == 0 ? K : tensor == 1 ? V : Q)
                       + ((size_t)(b * Ll + l) * Dd + d0);
    float4 a = *reinterpret_cast<const float4*>(src);
    float4 e = *reinterpret_cast<const float4*>(src + 4);
    if (tensor == 2) {
        a.x *= QSCALE; a.y *= QSCALE; a.z *= QSCALE; a.w *= QSCALE;
        e.x *= QSCALE; e.y *= QSCALE; e.z *= QSCALE; e.w *= QSCALE;
    }
    uint4 H = make_uint4(packh2(a.x, a.y), packh2(a.z, a.w),
                         packh2(e.x, e.y), packh2(e.z, e.w));
    int tile = l >> 7, row = l & 127;
    u32 off = swz((u32)(row * 128 + d0 * 2));
    unsigned char* oh = (tensor == 0 ? g_k : tensor == 1 ? g_v : g_q)[b][tile];
    *reinterpret_cast<uint4*>(oh + off) = H;
}

// ---------------- kernel 2: attention ----------------
__global__ void __launch_bounds__(NT, 2)
attn_mma(const float* __restrict__ QM, const float* __restrict__ KM,
         float* __restrict__ Out)
{
    extern __shared__ char sm[];
    const u32 smb = smem_u32(sm);
    const int tid = threadIdx.x, w = tid >> 5, L = tid & 31;
    const int b = blockIdx.y, qt = blockIdx.x, q0 = qt * TQ;
    const int mg = w >> 2, kq = w & 3;   // 2 row-groups x 4 key-quarters

    // init: Q (persistent 8KB) + tile0 KV + km0
    {
        const unsigned char* qsrc = g_q[b][qt >> 1] + (qt & 1) * 8192;
#pragma unroll
        for (int t = 0; t < 2; ++t) {
            u32 o = (u32)(tid + 256 * t) * 16;
            cpa16(smb + SM_Q + o, qsrc + o);
        }
#pragma unroll
        for (int t = 0; t < 4; ++t) {
            u32 o = (u32)(tid + 256 * t) * 16;
            cpa16(smb + OF_K + o, g_k[b][0] + o);
            cpa16(smb + OF_V + o, g_v[b][0] + o);
        }
        if (tid < 32) cpa16(smb + SM_KM + tid * 16, KM + b * Ll + tid * 4);
        cpa_commit();
        cpa_wait0();
        __syncthreads();
    }

    const int m = L >> 3;
    const u32 xm = (u32)(L & 7) << 4;
    const int arw = (m & 1) * 8 + (L & 7);
    const u32 acolsel = (u32)(m >> 1) * 16;
    const u32 krw_off = (u32)((m >> 1) * 8 + (L & 7)) * 128;
    const u32 kcolsel = (u32)(m & 1) * 16;
    const u32 vrw_off = (u32)arw * 128;
    const u32 vcolsel = (u32)(m >> 1) * 16;
    const u32 kqrow = (u32)(kq * 32);

    float oacc[2][8][4];
#pragma unroll
    for (int mt = 0; mt < 2; ++mt)
#pragma unroll
        for (int j = 0; j < 8; ++j)
            { oacc[mt][j][0] = 0; oacc[mt][j][1] = 0; oacc[mt][j][2] = 0; oacc[mt][j][3] = 0; }
    float rs[2][2] = {{0.f, 0.f}, {0.f, 0.f}};

    for (int kt = 0; kt < NTILES; ++kt) {
        const int cur = kt & 1;
        const u32 smc = smb + (u32)cur * BUFSZ;
        const bool pf = (kt + 1 < NTILES);
        if (pf) {
            const u32 sma = smb + (u32)(cur ^ 1) * BUFSZ;
            const int nt2 = kt + 1;
#pragma unroll
            for (int t = 0; t < 4; ++t) {
                u32 o = (u32)(tid + 256 * t) * 16;
                cpa16(sma + OF_K + o, g_k[b][nt2] + o);
                cpa16(sma + OF_V + o, g_v[b][nt2] + o);
            }
            if (tid < 32)
                cpa16(smb + SM_KM + (u32)(cur ^ 1) * 512 + tid * 16,
                      KM + b * Ll + nt2 * 128 + tid * 4);
            cpa_commit();
        }

        // ---- GEMM1: S[32 rows][32 keys] = Q @ K^T (fp16 single-pass) ----
        float sacc[2][4][4];
#pragma unroll
        for (int mt = 0; mt < 2; ++mt)
#pragma unroll
            for (int j = 0; j < 4; ++j)
                { sacc[mt][j][0] = 0; sacc[mt][j][1] = 0; sacc[mt][j][2] = 0; sacc[mt][j][3] = 0; }
#pragma unroll
        for (int kc = 0; kc < 4; ++kc) {
            u32 qcoff = (((u32)kc * 32 + acolsel) ^ xm);
            u32 qh0[4], qh1[4];
            ldsm4(qh0, smb + SM_Q + (u32)(mg * 32 + arw) * 128 + qcoff);
            ldsm4(qh1, smb + SM_Q + (u32)(mg * 32 + 16 + arw) * 128 + qcoff);
            u32 coff = (((u32)kc * 32 + kcolsel) ^ xm);
#pragma unroll
            for (int j2 = 0; j2 < 2; ++j2) {
                u32 bh[4];
                ldsm4(bh, smc + OF_K + (kqrow + (u32)j2 * 16) * 128 + krw_off + coff);
                mma16816(sacc[0][2 * j2],     qh0, bh[0], bh[1]);
                mma16816(sacc[0][2 * j2 + 1], qh0, bh[2], bh[3]);
                mma16816(sacc[1][2 * j2],     qh1, bh[0], bh[1]);
                mma16816(sacc[1][2 * j2 + 1], qh1, bh[2], bh[3]);
            }
        }

        // ---- softmax + GEMM2: O += P @ V (fp16, P in registers) ----
        const float* kmp = reinterpret_cast<const float*>(sm + SM_KM) + cur * 128 + kq * 32;
#pragma unroll
        for (int kc = 0; kc < 2; ++kc) {
            u32 Ah[2][4];
#pragma unroll
            for (int mt = 0; mt < 2; ++mt)
#pragma unroll
                for (int half = 0; half < 2; ++half) {
                    int j = 2 * kc + half;
                    float2 km2 = *reinterpret_cast<const float2*>(kmp + 8 * j + 2 * (L & 3));
                    float p0 = ex2f(sacc[mt][j][0]) * km2.x;
                    float p1 = ex2f(sacc[mt][j][1]) * km2.y;
                    float p2 = ex2f(sacc[mt][j][2]) * km2.x;
                    float p3 = ex2f(sacc[mt][j][3]) * km2.y;
                    rs[mt][0] += p0 + p1;
                    rs[mt][1] += p2 + p3;
                    Ah[mt][2 * half]     = packh2(p0, p1);
                    Ah[mt][2 * half + 1] = packh2(p2, p3);
                }
            u32 vbase = smc + OF_V + (kqrow + (u32)kc * 16) * 128 + vrw_off;
#pragma unroll
            for (int j2 = 0; j2 < 4; ++j2) {
                u32 vh[4];
                ldsm4t(vh, vbase + (((u32)j2 * 32 + vcolsel) ^ xm));
                mma16816(oacc[0][2 * j2],     Ah[0], vh[0], vh[1]);
                mma16816(oacc[0][2 * j2 + 1], Ah[0], vh[2], vh[3]);
                mma16816(oacc[1][2 * j2],     Ah[1], vh[0], vh[1]);
                mma16816(oacc[1][2 * j2 + 1], Ah[1], vh[2], vh[3]);
            }
        }

        if (pf) cpa_wait0();
        __syncthreads();
    }

    // ---- epilogue: quad-reduce rowsums, 4-way key-quarter combine ----
#pragma unroll
    for (int mt = 0; mt < 2; ++mt)
#pragma unroll
        for (int s = 0; s < 2; ++s) {
            rs[mt][s] += __shfl_xor_sync(0xFFFFFFFFu, rs[mt][s], 1);
            rs[mt][s] += __shfl_xor_sync(0xFFFFFFFFu, rs[mt][s], 2);
        }

    float* OS = reinterpret_cast<float*>(sm);            // 3 x [64][64] f32
    float* RS = reinterpret_cast<float*>(sm + 49152);    // 3 x [64]
    if (kq != 0) {
        const int ib = kq - 1;
#pragma unroll
        for (int mt = 0; mt < 2; ++mt) {
            int ra = mg * 32 + mt * 16 + (L >> 2);
            int rb = ra + 8;
#pragma unroll
            for (int j = 0; j < 8; ++j) {
                *reinterpret_cast<float2*>(&OS[ib * 4096 + ra * 64 + 8 * j + 2 * (L & 3)]) =
                    make_float2(oacc[mt][j][0], oacc[mt][j][1]);
                *reinterpret_cast<float2*>(&OS[ib * 4096 + rb * 64 + 8 * j + 2 * (L & 3)]) =
                    make_float2(oacc[mt][j][2], oacc[mt][j][3]);
            }
            if ((L & 3) == 0) { RS[ib * 64 + ra] = rs[mt][0]; RS[ib * 64 + rb] = rs[mt][1]; }
        }
    }
    __syncthreads();
    if (kq == 0) {
#pragma unroll
        for (int mt = 0; mt < 2; ++mt) {
            int ra = mg * 32 + mt * 16 + (L >> 2);
            int rb = ra + 8;
            float sa = rs[mt][0] + RS[ra] + RS[64 + ra] + RS[128 + ra];
            float sb = rs[mt][1] + RS[rb] + RS[64 + rb] + RS[128 + rb];
            float dva = QM[b * Ll + q0 + ra] / fmaxf(sa, 2e-15f);
            float dvb = QM[b * Ll + q0 + rb] / fmaxf(sb, 2e-15f);
            float* oa = Out + (size_t)(b * Ll + q0 + ra) * Dd + 2 * (L & 3);
            float* ob = Out + (size_t)(b * Ll + q0 + rb) * Dd + 2 * (L & 3);
#pragma unroll
            for (int j = 0; j < 8; ++j) {
                int ca = ra * 64 + 8 * j + 2 * (L & 3);
                int cb = rb * 64 + 8 * j + 2 * (L & 3);
                float2 u0 = *reinterpret_cast<const float2*>(&OS[ca]);
                float2 u1 = *reinterpret_cast<const float2*>(&OS[4096 + ca]);
                float2 u2 = *reinterpret_cast<const float2*>(&OS[8192 + ca]);
                float2 v0 = *reinterpret_cast<const float2*>(&OS[cb]);
                float2 v1 = *reinterpret_cast<const float2*>(&OS[4096 + cb]);
                float2 v2 = *reinterpret_cast<const float2*>(&OS[8192 + cb]);
                *reinterpret_cast<float2*>(oa + 8 * j) =
                    make_float2((oacc[mt][j][0] + u0.x + u1.x + u2.x) * dva,
                                (oacc[mt][j][1] + u0.y + u1.y + u2.y) * dva);
                *reinterpret_cast<float2*>(ob + 8 * j) =
                    make_float2((oacc[mt][j][2] + v0.x + v1.x + v2.x) * dvb,
                                (oacc[mt][j][3] + v0.y + v1.y + v2.y) * dvb);
            }
        }
    }
}

extern "C" void kernel_launch(void* const* d_in, const int* in_sizes, int n_in,
                              void* d_out, int out_size) {
    const float* Q  = (const float*)d_in[0];
    const float* K  = (const float*)d_in[1];
    const float* V  = (const float*)d_in[2];
    const float* QM = (const float*)d_in[3];
    const float* KM = (const float*)d_in[4];
    float* Out = (float*)d_out;

    presplit<<<dim3(512, 3), 256>>>(Q, K, V);

    cudaFuncSetAttribute(attn_mma, cudaFuncAttributeMaxDynamicSharedMemorySize, SM_TOT);
    dim3 grid(Ll / TQ, Bb);   // 32 q-tiles x 8 batches = 256 CTAs, 2 per SM
    attn_mma<<<grid, NT, SM_TOT>>>(QM, KM, Out);
}

// round 9
// speedup vs baseline: 6.1807x; 1.0580x over previous
#include <cuda_runtime.h>
#include <cuda_fp16.h>

typedef unsigned int u32;
#define DEVINL __device__ __forceinline__

static constexpr int Bb = 8, Ll = 2048, Dd = 64;
static constexpr int TQ = 128, NT = 512, NTILES = 16;
static constexpr int NSTAGE = 4;
static constexpr float QSCALE = 0.18033688011112042f; // log2(e)/8

// global scratch: fp16, tile-swizzled, contiguous 16KB per tile
__device__ __align__(16) unsigned char g_q[Bb][16][16384];
__device__ __align__(16) unsigned char g_k[Bb][16][16384];
__device__ __align__(16) unsigned char g_v[Bb][16][16384];

// smem layout
static constexpr int OF_K = 0;            // within a 32KB stage
static constexpr int OF_V = 16384;
static constexpr int STAGESZ = 32768;     // 4 stages: 0..131071
static constexpr int SM_Q  = 131072;      // fp16 [128][64] = 16KB
static constexpr int SM_KM = 147456;      // 2048 f32 = 8KB (whole batch row of KM)
static constexpr int SM_BAR = 155648;     // full[4] then empty[4], 8B each
static constexpr int SM_TOT = 155776;

DEVINL u32 smem_u32(const void* p) {
    u32 a;
    asm("{ .reg .u64 t; cvta.to.shared.u64 t, %1; cvt.u32.u64 %0, t; }" : "=r"(a) : "l"(p));
    return a;
}
DEVINL u32 swz(u32 o) { return o ^ ((o >> 3) & 0x70); }
DEVINL float ex2f(float x) { float r; asm("ex2.approx.f32 %0, %1;" : "=f"(r) : "f"(x)); return r; }
DEVINL u32 packh2(float lo, float hi) {
    u32 r; asm("cvt.rn.f16x2.f32 %0, %1, %2;" : "=r"(r) : "f"(hi), "f"(lo)); return r;
}

DEVINL void ldsm4(u32* r, u32 a) {
    asm volatile("ldmatrix.sync.aligned.m8n8.x4.shared.b16 {%0,%1,%2,%3}, [%4];"
                 : "=r"(r[0]), "=r"(r[1]), "=r"(r[2]), "=r"(r[3]) : "r"(a) : "memory");
}
DEVINL void ldsm4t(u32* r, u32 a) {
    asm volatile("ldmatrix.sync.aligned.m8n8.x4.trans.shared.b16 {%0,%1,%2,%3}, [%4];"
                 : "=r"(r[0]), "=r"(r[1]), "=r"(r[2]), "=r"(r[3]) : "r"(a) : "memory");
}
DEVINL void mma16816(float* c, const u32* a, u32 b0, u32 b1) {
    asm("mma.sync.aligned.m16n8k16.row.col.f32.f16.f16.f32 "
        "{%0,%1,%2,%3}, {%4,%5,%6,%7}, {%8,%9}, {%0,%1,%2,%3};"
        : "+f"(c[0]), "+f"(c[1]), "+f"(c[2]), "+f"(c[3])
        : "r"(a[0]), "r"(a[1]), "r"(a[2]), "r"(a[3]), "r"(b0), "r"(b1));
}

DEVINL void cpa16(u32 dst, const void* src) {
    asm volatile("cp.async.cg.shared.global [%0], [%1], 16;" :: "r"(dst), "l"(src) : "memory");
}
DEVINL void cpa_commit() { asm volatile("cp.async.commit_group;" ::: "memory"); }
DEVINL void cpa_wait0()  { asm volatile("cp.async.wait_group 0;" ::: "memory"); }

// ---- mbarrier / bulk-copy primitives (sm_90 PTX; no 'a' features) ----
DEVINL void mbar_init(u32 bar, u32 cnt) {
    asm volatile("mbarrier.init.shared.b64 [%0], %1;" :: "r"(bar), "r"(cnt) : "memory");
}
DEVINL void mbar_arrive(u32 bar) {
    asm volatile("mbarrier.arrive.shared.b64 _, [%0];" :: "r"(bar) : "memory");
}
DEVINL void mbar_expect_tx(u32 bar, u32 bytes) {
    asm volatile("mbarrier.arrive.expect_tx.shared.b64 _, [%0], %1;"
                 :: "r"(bar), "r"(bytes) : "memory");
}
DEVINL void mbar_wait(u32 bar, u32 parity) {
    asm volatile(
        "{\n\t.reg .pred P;\n\t"
        "WL_%=:\n\t"
        "mbarrier.try_wait.parity.acquire.cta.shared::cta.b64 P, [%0], %1, 0x989680;\n\t"
        "@P bra WD_%=;\n\t"
        "bra WL_%=;\n\t"
        "WD_%=:\n\t}"
        :: "r"(bar), "r"(parity) : "memory");
}
DEVINL void bulk_cp(u32 dst, const void* src, u32 bar) {
    asm volatile(
        "cp.async.bulk.shared::cta.global.mbarrier::complete_tx::bytes [%0], [%1], %2, [%3];"
        :: "r"(dst), "l"(src), "r"(16384u), "r"(bar) : "memory");
}

// ---------------- kernel 1: fp32 -> fp16, tile-swizzled ----------------
__global__ void __launch_bounds__(256, 4)
presplit(const float* __restrict__ Q, const float* __restrict__ K,
         const float* __restrict__ V)
{
    int tensor = blockIdx.y;                       // 0=K, 1=V, 2=Q(scaled)
    int c = blockIdx.x * 256 + threadIdx.x;
    int b  = c >> 14;
    int l  = (c >> 3) & 2047;
    int d0 = (c & 7) * 8;

    const float* src = (tensor == 0 ? K : tensor == 1 ? V : Q)
                       + ((size_t)(b * Ll + l) * Dd + d0);
    float4 a = *reinterpret_cast<const float4*>(src);
    float4 e = *reinterpret_cast<const float4*>(src + 4);
    if (tensor == 2) {
        a.x *= QSCALE; a.y *= QSCALE; a.z *= QSCALE; a.w *= QSCALE;
        e.x *= QSCALE; e.y *= QSCALE; e.z *= QSCALE; e.w *= QSCALE;
    }
    uint4 H = make_uint4(packh2(a.x, a.y), packh2(a.z, a.w),
                         packh2(e.x, e.y), packh2(e.z, e.w));
    int tile = l >> 7, row = l & 127;
    u32 off = swz((u32)(row * 128 + d0 * 2));
    unsigned char* oh = (tensor == 0 ? g_k : tensor == 1 ? g_v : g_q)[b][tile];
    *reinterpret_cast<uint4*>(oh + off) = H;
}

// ---------------- kernel 2: attention, mbarrier-pipelined ----------------
__global__ void __launch_bounds__(NT, 1)
attn_mma(const float* __restrict__ QM, const float* __restrict__ KM,
         float* __restrict__ Out)
{
    extern __shared__ char sm[];
    const u32 smb = smem_u32(sm);
    const int tid = threadIdx.x, w = tid >> 5, L = tid & 31;
    const int b = blockIdx.y, qt = blockIdx.x, q0 = qt * TQ;
    const int mg = w >> 2, kq = w & 3;   // 4 row-groups x 4 key-quarters

    // init: Q (16KB) + km (8KB whole batch) via per-thread cp.async; barriers
    {
        u32 o = (u32)tid * 16;
        cpa16(smb + SM_Q + o, g_q[b][qt] + o * 2 / 2);            // 512*16 = 8KB... two rounds:
        cpa16(smb + SM_Q + 8192 + o, g_q[b][qt] + 8192 + o);
        cpa16(smb + SM_KM + o, KM + b * Ll + tid * 4);
        // fix first Q round address (tid*16 straightforward)
        cpa_commit();
        if (tid == 0) {
#pragma unroll
            for (int s = 0; s < NSTAGE; ++s) {
                mbar_init(smb + SM_BAR + s * 8, 1);        // full
                mbar_init(smb + SM_BAR + 32 + s * 8, 16);  // empty: 16 warps
            }
        }
        cpa_wait0();
        __syncthreads();
    }

    // producer prologue: issue stages 0..2
    if (tid == 0) {
#pragma unroll
        for (int it = 0; it < 3; ++it) {
            u32 s = (u32)it & 3;
            u32 fb = smb + SM_BAR + s * 8;
            mbar_wait(smb + SM_BAR + 32 + s * 8, 1u);      // fresh -> immediate
            mbar_expect_tx(fb, 32768u);
            bulk_cp(smb + s * STAGESZ + OF_K, g_k[b][it], fb);
            bulk_cp(smb + s * STAGESZ + OF_V, g_v[b][it], fb);
        }
    }

    // lane addressing (invariant registers)
    const int m = L >> 3;
    const u32 xm = (u32)(L & 7) << 4;
    const int arw = (m & 1) * 8 + (L & 7);
    const u32 acolsel = (u32)(m >> 1) * 16;
    const u32 krw_off = (u32)((m >> 1) * 8 + (L & 7)) * 128;
    const u32 kcolsel = (u32)(m & 1) * 16;
    const u32 vrw_off = (u32)arw * 128;
    const u32 vcolsel = (u32)(m >> 1) * 16;
    const u32 kqrow = (u32)(kq * 32);

    u32 qaddr[4][2], koff[4], voff[4];
#pragma unroll
    for (int kc = 0; kc < 4; ++kc) {
        u32 qcoff = (((u32)kc * 32 + acolsel) ^ xm);
        qaddr[kc][0] = smb + SM_Q + (u32)(mg * 32 + arw) * 128 + qcoff;
        qaddr[kc][1] = smb + SM_Q + (u32)(mg * 32 + 16 + arw) * 128 + qcoff;
        koff[kc] = OF_K + kqrow * 128 + krw_off + (((u32)kc * 32 + kcolsel) ^ xm);
        voff[kc] = OF_V + kqrow * 128 + vrw_off + (((u32)kc * 32 + vcolsel) ^ xm);
    }
    const float* km_base = reinterpret_cast<const float*>(sm + SM_KM) + kq * 32 + 2 * (L & 3);

    float oacc[2][8][4];
#pragma unroll
    for (int mt = 0; mt < 2; ++mt)
#pragma unroll
        for (int j = 0; j < 8; ++j)
            { oacc[mt][j][0] = 0; oacc[mt][j][1] = 0; oacc[mt][j][2] = 0; oacc[mt][j][3] = 0; }
    float rs[2][2] = {{0.f, 0.f}, {0.f, 0.f}};

    for (int kt = 0; kt < NTILES; ++kt) {
        const u32 s = (u32)kt & 3;
        const u32 sbase = smb + s * STAGESZ;
        const u32 parity = ((u32)kt >> 2) & 1u;
        mbar_wait(smb + SM_BAR + s * 8, parity);

        // ---- GEMM1: S[32 rows][32 keys] = Q @ K^T ----
        float sacc[2][4][4];
#pragma unroll
        for (int mt = 0; mt < 2; ++mt)
#pragma unroll
            for (int j = 0; j < 4; ++j)
                { sacc[mt][j][0] = 0; sacc[mt][j][1] = 0; sacc[mt][j][2] = 0; sacc[mt][j][3] = 0; }
#pragma unroll
        for (int kc = 0; kc < 4; ++kc) {
            u32 qh0[4], qh1[4];
            ldsm4(qh0, qaddr[kc][0]);
            ldsm4(qh1, qaddr[kc][1]);
#pragma unroll
            for (int j2 = 0; j2 < 2; ++j2) {
                u32 bh[4];
                ldsm4(bh, sbase + koff[kc] + (u32)j2 * 2048);
                mma16816(sacc[0][2 * j2],     qh0, bh[0], bh[1]);
                mma16816(sacc[0][2 * j2 + 1], qh0, bh[2], bh[3]);
                mma16816(sacc[1][2 * j2],     qh1, bh[0], bh[1]);
                mma16816(sacc[1][2 * j2 + 1], qh1, bh[2], bh[3]);
            }
        }

        // ---- softmax + GEMM2: O += P @ V ----
        const float* kmp = km_base + kt * 128;
#pragma unroll
        for (int kc = 0; kc < 2; ++kc) {
            u32 Ah[2][4];
#pragma unroll
            for (int mt = 0; mt < 2; ++mt)
#pragma unroll
                for (int half = 0; half < 2; ++half) {
                    int j = 2 * kc + half;
                    float2 km2 = *reinterpret_cast<const float2*>(kmp + 8 * j);
                    float p0 = ex2f(sacc[mt][j][0]) * km2.x;
                    float p1 = ex2f(sacc[mt][j][1]) * km2.y;
                    float p2 = ex2f(sacc[mt][j][2]) * km2.x;
                    float p3 = ex2f(sacc[mt][j][3]) * km2.y;
                    rs[mt][0] += p0 + p1;
                    rs[mt][1] += p2 + p3;
                    Ah[mt][2 * half]     = packh2(p0, p1);
                    Ah[mt][2 * half + 1] = packh2(p2, p3);
                }
#pragma unroll
            for (int j2 = 0; j2 < 4; ++j2) {
                u32 vh[4];
                ldsm4t(vh, sbase + voff[j2] + (u32)kc * 2048);
                mma16816(oacc[0][2 * j2],     Ah[0], vh[0], vh[1]);
                mma16816(oacc[0][2 * j2 + 1], Ah[0], vh[2], vh[3]);
                mma16816(oacc[1][2 * j2],     Ah[1], vh[0], vh[1]);
                mma16816(oacc[1][2 * j2 + 1], Ah[1], vh[2], vh[3]);
            }
        }

        // done reading stage s
        if (L == 0) mbar_arrive(smb + SM_BAR + 32 + s * 8);

        // producer: issue tile kt+3
        if (tid == 0 && kt + 3 < NTILES) {
            const int it = kt + 3;
            u32 s2 = (u32)it & 3;
            u32 fb = smb + SM_BAR + s2 * 8;
            mbar_wait(smb + SM_BAR + 32 + s2 * 8, ((((u32)it >> 2) & 1u) ^ 1u));
            mbar_expect_tx(fb, 32768u);
            bulk_cp(smb + s2 * STAGESZ + OF_K, g_k[b][it], fb);
            bulk_cp(smb + s2 * STAGESZ + OF_V, g_v[b][it], fb);
        }
    }

    // ---- epilogue: quad-reduce rowsums, 4-way key-quarter combine ----
#pragma unroll
    for (int mt = 0; mt < 2; ++mt)
#pragma unroll
        for (int sdx = 0; sdx < 2; ++sdx) {
            rs[mt][sdx] += __shfl_xor_sync(0xFFFFFFFFu, rs[mt][sdx], 1);
            rs[mt][sdx] += __shfl_xor_sync(0xFFFFFFFFu, rs[mt][sdx], 2);
        }
    __syncthreads();   // pipeline fully drained; smem stages reusable

    float* OS = reinterpret_cast<float*>(sm);            // 3 x [128][64] f32
    float* RS = reinterpret_cast<float*>(sm + 98304);    // 3 x [128]
    if (kq != 0) {
        const int ib = kq - 1;
#pragma unroll
        for (int mt = 0; mt < 2; ++mt) {
            int ra = mg * 32 + mt * 16 + (L >> 2);
            int rb = ra + 8;
#pragma unroll
            for (int j = 0; j < 8; ++j) {
                *reinterpret_cast<float2*>(&OS[ib * 8192 + ra * 64 + 8 * j + 2 * (L & 3)]) =
                    make_float2(oacc[mt][j][0], oacc[mt][j][1]);
                *reinterpret_cast<float2*>(&OS[ib * 8192 + rb * 64 + 8 * j + 2 * (L & 3)]) =
                    make_float2(oacc[mt][j][2], oacc[mt][j][3]);
            }
            if ((L & 3) == 0) { RS[ib * 128 + ra] = rs[mt][0]; RS[ib * 128 + rb] = rs[mt][1]; }
        }
    }
    __syncthreads();
    if (kq == 0) {
#pragma unroll
        for (int mt = 0; mt < 2; ++mt) {
            int ra = mg * 32 + mt * 16 + (L >> 2);
            int rb = ra + 8;
            float sa = rs[mt][0] + RS[ra] + RS[128 + ra] + RS[256 + ra];
            float sb = rs[mt][1] + RS[rb] + RS[128 + rb] + RS[256 + rb];
            float dva = QM[b * Ll + q0 + ra] / fmaxf(sa, 2e-15f);
            float dvb = QM[b * Ll + q0 + rb] / fmaxf(sb, 2e-15f);
            float* oa = Out + (size_t)(b * Ll + q0 + ra) * Dd + 2 * (L & 3);
            float* ob = Out + (size_t)(b * Ll + q0 + rb) * Dd + 2 * (L & 3);
#pragma unroll
            for (int j = 0; j < 8; ++j) {
                int ca = ra * 64 + 8 * j + 2 * (L & 3);
                int cb = rb * 64 + 8 * j + 2 * (L & 3);
                float2 u0 = *reinterpret_cast<const float2*>(&OS[ca]);
                float2 u1 = *reinterpret_cast<const float2*>(&OS[8192 + ca]);
                float2 u2 = *reinterpret_cast<const float2*>(&OS[16384 + ca]);
                float2 v0 = *reinterpret_cast<const float2*>(&OS[cb]);
                float2 v1 = *reinterpret_cast<const float2*>(&OS[8192 + cb]);
                float2 v2 = *reinterpret_cast<const float2*>(&OS[16384 + cb]);
                *reinterpret_cast<float2*>(oa + 8 * j) =
                    make_float2((oacc[mt][j][0] + u0.x + u1.x + u2.x) * dva,
                                (oacc[mt][j][1] + u0.y + u1.y + u2.y) * dva);
                *reinterpret_cast<float2*>(ob + 8 * j) =
                    make_float2((oacc[mt][j][2] + v0.x + v1.x + v2.x) * dvb,
                                (oacc[mt][j][3] + v0.y + v1.y + v2.y) * dvb);
            }
        }
    }
}

extern "C" void kernel_launch(void* const* d_in, const int* in_sizes, int n_in,
                              void* d_out, int out_size) {
    const float* Q  = (const float*)d_in[0];
    const float* K  = (const float*)d_in[1];
    const float* V  = (const float*)d_in[2];
    const float* QM = (const float*)d_in[3];
    const float* KM = (const float*)d_in[4];
    float* Out = (float*)d_out;

    presplit<<<dim3(512, 3), 256>>>(Q, K, V);

    cudaFuncSetAttribute(attn_mma, cudaFuncAttributeMaxDynamicSharedMemorySize, SM_TOT);
    dim3 grid(Ll / TQ, Bb);   // 16 q-tiles x 8 batches = 128 CTAs, 1 per SM
    attn_mma<<<grid, NT, SM_TOT>>>(QM, KM, Out);
}